// round 2
// baseline (speedup 1.0000x reference)
#include <cuda_runtime.h>

#define Bb 32
#define Ll 1024
#define Dd 1024
#define Hh 16
#define DVv 64

// Scratch (allocation-free rule: __device__ globals)
__device__ float g_q[Bb*Dd];        // q[b][j], j = h*64+dv
__device__ float g_G[Bb*Dd*Hh];     // G[b][din][h] = sum_dv wk[din][h*64+dv]*q[b][h*64+dv]
__device__ float g_c[Bb*Hh];        // bk . q_h
__device__ float g_S[Bb*Hh*Ll];     // scores [b][h][l]
__device__ float g_A[Bb*Ll*Hh];     // log-softmax attn, transposed [b][l][h]

// ---------------- Kernel 1: q = x[:, -1, :] @ wq + bq ----------------
__global__ void k_q(const float* __restrict__ x, const float* __restrict__ wq,
                    const float* __restrict__ bq) {
    __shared__ float xs[Dd];
    int b = blockIdx.x, jc = blockIdx.y;
    const float* xr = x + ((size_t)b*Ll + (Ll-1))*Dd;
    for (int i = threadIdx.x; i < Dd; i += 128) xs[i] = xr[i];
    __syncthreads();
    int j = jc*128 + threadIdx.x;
    float acc = bq[j];
    #pragma unroll 4
    for (int d = 0; d < Dd; d++) acc += xs[d] * wq[(size_t)d*Dd + j];
    g_q[b*Dd + j] = acc;
}

// ---------------- Kernel 2: G[b][din][h] ----------------
__global__ void k_G(const float* __restrict__ wk) {
    __shared__ float qs[Dd];
    int b = blockIdx.x;
    for (int i = threadIdx.x; i < Dd; i += 256) qs[i] = g_q[b*Dd + i];
    __syncthreads();
    int warp = threadIdx.x >> 5, lane = threadIdx.x & 31;
    int din = blockIdx.y*8 + warp;
    const float* wrow = wk + (size_t)din*Dd;
    float mine = 0.f;
    #pragma unroll 4
    for (int k = 0; k < 32; k++) {
        int j = k*32 + lane;              // j in [32k, 32k+31]: all same head k>>1
        float p = wrow[j] * qs[j];
        #pragma unroll
        for (int o = 16; o > 0; o >>= 1) p += __shfl_xor_sync(0xffffffffu, p, o);
        if (lane == (k >> 1)) mine += p;
    }
    if (lane < Hh) g_G[((size_t)b*Dd + din)*Hh + lane] = mine;
}

// ---------------- Kernel 2b: c[b][h] = bk . q_h ----------------
__global__ void k_c(const float* __restrict__ bk) {
    int t = blockIdx.x*blockDim.x + threadIdx.x;   // 512 total
    if (t >= Bb*Hh) return;
    int b = t >> 4, h = t & 15;
    float acc = 0.f;
    #pragma unroll 8
    for (int dv = 0; dv < DVv; dv++) {
        int j = h*DVv + dv;
        acc += bk[j] * g_q[b*Dd + j];
    }
    g_c[t] = acc;
}

// ---------------- Kernel 3: scores s[b][h][l] ----------------
#define GP 1028   // padded pitch for Gs rows (multiple of 4 for float4, breaks bank alias)
__global__ void k_scores(const float* __restrict__ x) {
    extern __shared__ float sm[];
    float* Xs = sm;              // [16][1024]
    float* Gs = sm + 16*Dd;      // [16][GP]  (Gs[h][din])
    int b = blockIdx.x, lt = blockIdx.y;
    int l0 = lt*16;
    const float4* xb4 = (const float4*)(x + ((size_t)b*Ll + l0)*Dd);
    for (int i = threadIdx.x; i < 16*Dd/4; i += 256) ((float4*)Xs)[i] = xb4[i];
    const float* gb = g_G + (size_t)b*Dd*Hh;
    for (int i = threadIdx.x; i < Dd*Hh; i += 256) {
        int din = i >> 4, h = i & 15;
        Gs[h*GP + din] = gb[i];
    }
    __syncthreads();
    int lw = threadIdx.x >> 4, h = threadIdx.x & 15;
    const float4* xr = (const float4*)(Xs + lw*Dd);
    const float4* gr = (const float4*)(Gs + h*GP);
    float acc = 0.f;
    #pragma unroll 8
    for (int i = 0; i < Dd/4; i++) {
        float4 a = xr[i], g = gr[i];
        acc += a.x*g.x + a.y*g.y + a.z*g.z + a.w*g.w;
    }
    int l = l0 + lw;
    float rate = (float)(Ll - l - 1) * (1.0f/Ll) + 1.0f;
    float invtemp = 1.0f / (32.0f + 1e-5f);
    g_S[((size_t)b*Hh + h)*Ll + l] = rate * (acc + g_c[b*Hh + h]) * invtemp;
}

// ---------------- Kernel 4: log-softmax over l ----------------
__global__ void k_lsm() {
    int bh = blockIdx.x;
    const float* s = g_S + (size_t)bh*Ll;
    __shared__ float red[8], red2[8];
    int tid = threadIdx.x, lane = tid & 31, warp = tid >> 5;
    float v[4]; float mx = -3.4e38f;
    #pragma unroll
    for (int i = 0; i < 4; i++) { v[i] = s[tid + 256*i]; mx = fmaxf(mx, v[i]); }
    #pragma unroll
    for (int o = 16; o > 0; o >>= 1) mx = fmaxf(mx, __shfl_xor_sync(0xffffffffu, mx, o));
    if (lane == 0) red[warp] = mx;
    __syncthreads();
    mx = red[0];
    #pragma unroll
    for (int i = 1; i < 8; i++) mx = fmaxf(mx, red[i]);
    float sum = 0.f;
    #pragma unroll
    for (int i = 0; i < 4; i++) sum += expf(v[i] - mx);
    #pragma unroll
    for (int o = 16; o > 0; o >>= 1) sum += __shfl_xor_sync(0xffffffffu, sum, o);
    if (lane == 0) red2[warp] = sum;
    __syncthreads();
    float tot = 0.f;
    #pragma unroll
    for (int i = 0; i < 8; i++) tot += red2[i];
    float lse = mx + logf(tot);
    int b = bh >> 4, h = bh & 15;
    #pragma unroll
    for (int i = 0; i < 4; i++) {
        int l = tid + 256*i;
        g_A[((size_t)b*Ll + l)*Hh + h] = v[i] - lse;
    }
}

// ---------- Kernel 5: fused V GEMM + attn*v*rate + residual + LayerNorm ----------
__global__ void __launch_bounds__(256) k_vgemm(
    const float* __restrict__ x, const float* __restrict__ wv,
    const float* __restrict__ bv, const float* __restrict__ gamma,
    const float* __restrict__ beta, float* __restrict__ out)
{
    __shared__ __align__(16) float Ws[8][Dd];   // 32 KB
    __shared__ float Xs[16][8];
    __shared__ float rsum[16][2], rsq[16][2];
    int tid = threadIdx.x;
    int tx = tid & 63, rg = tid >> 6;           // cols group / row group
    int row0 = blockIdx.x * 16;
    float4 acc[4][4];
    #pragma unroll
    for (int i = 0; i < 4; i++)
        #pragma unroll
        for (int c = 0; c < 4; c++) acc[i][c] = make_float4(0.f,0.f,0.f,0.f);

    for (int k0 = 0; k0 < Dd; k0 += 8) {
        #pragma unroll
        for (int it = 0; it < 8; it++) {
            int i4 = it*256 + tid;
            int kk = i4 >> 8, c4 = i4 & 255;
            ((float4*)Ws[kk])[c4] = ((const float4*)(wv + (size_t)(k0+kk)*Dd))[c4];
        }
        if (tid < 128)
            Xs[tid >> 3][tid & 7] = x[(size_t)(row0 + (tid >> 3))*Dd + k0 + (tid & 7)];
        __syncthreads();
        #pragma unroll
        for (int kk = 0; kk < 8; kk++) {
            float xv0 = Xs[rg][kk], xv1 = Xs[rg+4][kk],
                  xv2 = Xs[rg+8][kk], xv3 = Xs[rg+12][kk];
            #pragma unroll
            for (int c = 0; c < 4; c++) {
                float4 w = ((float4*)Ws[kk])[tx + 64*c];
                acc[0][c].x += xv0*w.x; acc[0][c].y += xv0*w.y; acc[0][c].z += xv0*w.z; acc[0][c].w += xv0*w.w;
                acc[1][c].x += xv1*w.x; acc[1][c].y += xv1*w.y; acc[1][c].z += xv1*w.z; acc[1][c].w += xv1*w.w;
                acc[2][c].x += xv2*w.x; acc[2][c].y += xv2*w.y; acc[2][c].z += xv2*w.z; acc[2][c].w += xv2*w.w;
                acc[3][c].x += xv3*w.x; acc[3][c].y += xv3*w.y; acc[3][c].z += xv3*w.z; acc[3][c].w += xv3*w.w;
            }
        }
        __syncthreads();
    }

    // ---- Epilogue: out_pre = A[b,l,h]*rate*(acc+bv) + x ; then LN ----
    int b = row0 >> 10;
    int lane = tid & 31, wp = (tid >> 5) & 1;
    float psum[4], psq[4];
    #pragma unroll
    for (int i = 0; i < 4; i++) {
        int r = rg + 4*i;
        int row = row0 + r;
        int l = row & (Ll - 1);
        float rate = (float)(Ll - l - 1) * (1.0f/Ll) + 1.0f;
        const float4* xrow4 = (const float4*)(x + (size_t)row*Dd);
        const float* Arow = g_A + ((size_t)b*Ll + l)*Hh;
        float s = 0.f, sq = 0.f;
        #pragma unroll
        for (int c = 0; c < 4; c++) {
            int j4 = tx + 64*c;
            int h = j4 >> 4;
            float a = Arow[h] * rate;
            float4 bvv = ((const float4*)bv)[j4];
            float4 xr = xrow4[j4];
            float4 t;
            t.x = a*(acc[i][c].x + bvv.x) + xr.x;
            t.y = a*(acc[i][c].y + bvv.y) + xr.y;
            t.z = a*(acc[i][c].z + bvv.z) + xr.z;
            t.w = a*(acc[i][c].w + bvv.w) + xr.w;
            acc[i][c] = t;
            s  += t.x + t.y + t.z + t.w;
            sq += t.x*t.x + t.y*t.y + t.z*t.z + t.w*t.w;
        }
        psum[i] = s; psq[i] = sq;
    }
    #pragma unroll
    for (int o = 16; o > 0; o >>= 1) {
        #pragma unroll
        for (int i = 0; i < 4; i++) {
            psum[i] += __shfl_xor_sync(0xffffffffu, psum[i], o);
            psq[i]  += __shfl_xor_sync(0xffffffffu, psq[i], o);
        }
    }
    if (lane == 0) {
        #pragma unroll
        for (int i = 0; i < 4; i++) { rsum[rg+4*i][wp] = psum[i]; rsq[rg+4*i][wp] = psq[i]; }
    }
    __syncthreads();
    #pragma unroll
    for (int i = 0; i < 4; i++) {
        int r = rg + 4*i;
        int row = row0 + r;
        float sm2 = rsum[r][0] + rsum[r][1];
        float sq2 = rsq[r][0]  + rsq[r][1];
        float mean = sm2 * (1.0f/1024.0f);
        float var  = sq2 * (1.0f/1024.0f) - mean*mean;
        float rstd = rsqrtf(var + 1e-5f);
        float4* orow = (float4*)(out + (size_t)row*Dd);
        #pragma unroll
        for (int c = 0; c < 4; c++) {
            int j4 = tx + 64*c;
            float4 g4 = ((const float4*)gamma)[j4];
            float4 b4 = ((const float4*)beta)[j4];
            float4 t = acc[i][c];
            float4 r4;
            r4.x = (t.x - mean)*rstd*g4.x + b4.x;
            r4.y = (t.y - mean)*rstd*g4.y + b4.y;
            r4.z = (t.z - mean)*rstd*g4.z + b4.z;
            r4.w = (t.w - mean)*rstd*g4.w + b4.w;
            orow[j4] = r4;
        }
    }
}

extern "C" void kernel_launch(void* const* d_in, const int* in_sizes, int n_in,
                              void* d_out, int out_size) {
    const float* x     = (const float*)d_in[0];
    const float* wq    = (const float*)d_in[1];
    const float* bq    = (const float*)d_in[2];
    const float* wk    = (const float*)d_in[3];
    const float* bk    = (const float*)d_in[4];
    const float* wv    = (const float*)d_in[5];
    const float* bv    = (const float*)d_in[6];
    const float* gamma = (const float*)d_in[7];
    const float* beta  = (const float*)d_in[8];
    float* out = (float*)d_out;

    k_q<<<dim3(Bb, 8), 128>>>(x, wq, bq);
    k_G<<<dim3(Bb, 128), 256>>>(wk);
    k_c<<<2, 256>>>(bk);

    size_t sm3 = (size_t)(16*Dd + 16*GP) * sizeof(float);   // ~128.3 KB
    cudaFuncSetAttribute(k_scores, cudaFuncAttributeMaxDynamicSharedMemorySize, (int)sm3);
    k_scores<<<dim3(Bb, 64), 256, sm3>>>(x);

    k_lsm<<<Bb*Hh, 256>>>();

    k_vgemm<<<(Bb*Ll)/16, 256>>>(x, wv, bv, gamma, beta, out);
}

// round 4
// speedup vs baseline: 2.8518x; 2.8518x over previous
#include <cuda_runtime.h>
#include <cuda_fp16.h>
#include <cstdint>

#define Bb 32
#define Ll 1024
#define Dd 1024
#define Hh 16
#define DVv 64

// ---------------- device-global scratch ----------------
__device__ float g_q[Bb*Dd];
__device__ float g_G[Bb*Dd*Hh];
__device__ float g_c[Bb*Hh];
__device__ float g_S[Bb*Hh*Ll];
__device__ float g_A[Bb*Ll*Hh];
__device__ __half g_Xh[(size_t)Bb*Ll*Dd];   // 64 MB
__device__ __half g_Xl[(size_t)Bb*Ll*Dd];   // 64 MB
__device__ __half g_Wth[(size_t)Dd*Dd];     // Wv^T hi  [n][k]
__device__ __half g_Wtl[(size_t)Dd*Dd];     // Wv^T lo  [n][k]

__device__ __forceinline__ uint32_t smem_to_u32(const void* p) {
    uint32_t a;
    asm("{ .reg .u64 t; cvta.to.shared.u64 t, %1; cvt.u32.u64 %0, t; }" : "=r"(a) : "l"(p));
    return a;
}
__device__ __forceinline__ void cp16(uint32_t saddr, const void* g) {
    asm volatile("cp.async.cg.shared.global [%0], [%1], 16;" :: "r"(saddr), "l"(g));
}
#define CP_COMMIT() asm volatile("cp.async.commit_group;" ::: "memory")
#define CP_WAIT(n)  asm volatile("cp.async.wait_group %0;" :: "n"(n) : "memory")

#define LDM4(R, addr) \
    asm volatile("ldmatrix.sync.aligned.m8n8.x4.shared.b16 {%0,%1,%2,%3}, [%4];" \
        : "=r"((R)[0]), "=r"((R)[1]), "=r"((R)[2]), "=r"((R)[3]) : "r"(addr))

#define MMA(D, A, B) \
    asm volatile("mma.sync.aligned.m16n8k16.row.col.f32.f16.f16.f32 " \
        "{%0,%1,%2,%3},{%4,%5,%6,%7},{%8,%9},{%0,%1,%2,%3};" \
        : "+f"((D)[0]), "+f"((D)[1]), "+f"((D)[2]), "+f"((D)[3]) \
        : "r"((A)[0]), "r"((A)[1]), "r"((A)[2]), "r"((A)[3]), "r"((B)[0]), "r"((B)[1]))

// ---------------- prep: split X into fp16 hi/lo ----------------
__global__ void k_split_x(const float* __restrict__ x) {
    size_t i = (size_t)blockIdx.x * 256 + threadIdx.x;   // float4 index
    float4 v = ((const float4*)x)[i];
    __half h0 = __float2half(v.x), h1 = __float2half(v.y);
    __half h2 = __float2half(v.z), h3 = __float2half(v.w);
    __half l0 = __float2half(v.x - __half2float(h0));
    __half l1 = __float2half(v.y - __half2float(h1));
    __half l2 = __float2half(v.z - __half2float(h2));
    __half l3 = __float2half(v.w - __half2float(h3));
    uint2 uh, ul;
    uh.x = ((uint32_t)__half_as_ushort(h1) << 16) | __half_as_ushort(h0);
    uh.y = ((uint32_t)__half_as_ushort(h3) << 16) | __half_as_ushort(h2);
    ul.x = ((uint32_t)__half_as_ushort(l1) << 16) | __half_as_ushort(l0);
    ul.y = ((uint32_t)__half_as_ushort(l3) << 16) | __half_as_ushort(l2);
    ((uint2*)g_Xh)[i] = uh;
    ((uint2*)g_Xl)[i] = ul;
}

// ---------------- prep: transpose + split Wv ----------------
__global__ void k_split_wT(const float* __restrict__ wv) {
    __shared__ float t[32][33];
    int k0 = blockIdx.y * 32, n0 = blockIdx.x * 32;
    int tx = threadIdx.x, ty = threadIdx.y;   // (32, 8)
    #pragma unroll
    for (int j = 0; j < 32; j += 8)
        t[ty + j][tx] = wv[(size_t)(k0 + ty + j) * Dd + n0 + tx];
    __syncthreads();
    #pragma unroll
    for (int j = 0; j < 32; j += 8) {
        float v = t[tx][ty + j];
        __half h = __float2half(v);
        size_t o = (size_t)(n0 + ty + j) * Dd + k0 + tx;
        g_Wth[o] = h;
        g_Wtl[o] = __float2half(v - __half2float(h));
    }
}

// ---------------- Kernel 1: q = x[:, -1, :] @ wq + bq ----------------
__global__ void k_q(const float* __restrict__ x, const float* __restrict__ wq,
                    const float* __restrict__ bq) {
    __shared__ float xs[Dd];
    int b = blockIdx.x, jc = blockIdx.y;
    const float* xr = x + ((size_t)b*Ll + (Ll-1))*Dd;
    for (int i = threadIdx.x; i < Dd; i += 128) xs[i] = xr[i];
    __syncthreads();
    int j = jc*128 + threadIdx.x;
    float acc = bq[j];
    #pragma unroll 4
    for (int d = 0; d < Dd; d++) acc += xs[d] * wq[(size_t)d*Dd + j];
    g_q[b*Dd + j] = acc;
}

// ---------------- Kernel 2: G[b][din][h] ----------------
__global__ void k_G(const float* __restrict__ wk) {
    __shared__ float qs[Dd];
    int b = blockIdx.x;
    for (int i = threadIdx.x; i < Dd; i += 256) qs[i] = g_q[b*Dd + i];
    __syncthreads();
    int warp = threadIdx.x >> 5, lane = threadIdx.x & 31;
    int din = blockIdx.y*8 + warp;
    const float* wrow = wk + (size_t)din*Dd;
    float mine = 0.f;
    #pragma unroll 4
    for (int k = 0; k < 32; k++) {
        int j = k*32 + lane;
        float p = wrow[j] * qs[j];
        #pragma unroll
        for (int o = 16; o > 0; o >>= 1) p += __shfl_xor_sync(0xffffffffu, p, o);
        if (lane == (k >> 1)) mine += p;
    }
    if (lane < Hh) g_G[((size_t)b*Dd + din)*Hh + lane] = mine;
}

// ---------------- Kernel 2b ----------------
__global__ void k_c(const float* __restrict__ bk) {
    int t = blockIdx.x*blockDim.x + threadIdx.x;
    if (t >= Bb*Hh) return;
    int b = t >> 4, h = t & 15;
    float acc = 0.f;
    #pragma unroll 8
    for (int dv = 0; dv < DVv; dv++) {
        int j = h*DVv + dv;
        acc += bk[j] * g_q[b*Dd + j];
    }
    g_c[t] = acc;
}

// ---------------- Kernel 3: scores (register-tiled) ----------------
__global__ void __launch_bounds__(128) k_scores(const float* __restrict__ x) {
    __shared__ __align__(16) float Xs[128][68];
    __shared__ __align__(16) float Gs[16][72];
    int b = blockIdx.x, lt = blockIdx.y;
    int l0 = lt * 128;
    int tid = threadIdx.x;
    int tx = tid & 7, ty = tid >> 3;
    float acc[8][2];
    #pragma unroll
    for (int j = 0; j < 8; j++) { acc[j][0] = 0.f; acc[j][1] = 0.f; }
    const float* xb = x + ((size_t)b*Ll + l0)*Dd;
    const float* gb = g_G + (size_t)b*Dd*Hh;

    for (int k0 = 0; k0 < Dd; k0 += 64) {
        #pragma unroll
        for (int it = 0; it < 16; it++) {
            int i = tid + 128*it;
            int row = i >> 4, ks = i & 15;
            ((float4*)&Xs[row][0])[ks] = ((const float4*)(xb + (size_t)row*Dd + k0))[ks];
        }
        #pragma unroll
        for (int it = 0; it < 8; it++) {
            int e = tid + 128*it;
            int din = e >> 4, h = e & 15;
            Gs[h][din] = gb[(size_t)(k0 + din)*Hh + h];
        }
        __syncthreads();
        #pragma unroll
        for (int k4 = 0; k4 < 16; k4++) {
            float4 g0 = ((float4*)&Gs[2*tx][0])[k4];
            float4 g1 = ((float4*)&Gs[2*tx+1][0])[k4];
            #pragma unroll
            for (int j = 0; j < 8; j++) {
                float4 xv = ((float4*)&Xs[ty + 16*j][0])[k4];
                acc[j][0] += xv.x*g0.x + xv.y*g0.y + xv.z*g0.z + xv.w*g0.w;
                acc[j][1] += xv.x*g1.x + xv.y*g1.y + xv.z*g1.z + xv.w*g1.w;
            }
        }
        __syncthreads();
    }
    float invtemp = 1.0f / (32.0f + 1e-5f);
    float c0 = g_c[b*Hh + 2*tx], c1 = g_c[b*Hh + 2*tx + 1];
    #pragma unroll
    for (int j = 0; j < 8; j++) {
        int l = l0 + ty + 16*j;
        float rate = (float)(Ll - l - 1) * (1.0f/Ll) + 1.0f;
        g_S[((size_t)b*Hh + 2*tx)*Ll + l]     = rate * (acc[j][0] + c0) * invtemp;
        g_S[((size_t)b*Hh + 2*tx + 1)*Ll + l] = rate * (acc[j][1] + c1) * invtemp;
    }
}

// ---------------- Kernel 4: log-softmax ----------------
__global__ void k_lsm() {
    int bh = blockIdx.x;
    const float* s = g_S + (size_t)bh*Ll;
    __shared__ float red[8], red2[8];
    int tid = threadIdx.x, lane = tid & 31, warp = tid >> 5;
    float v[4]; float mx = -3.4e38f;
    #pragma unroll
    for (int i = 0; i < 4; i++) { v[i] = s[tid + 256*i]; mx = fmaxf(mx, v[i]); }
    #pragma unroll
    for (int o = 16; o > 0; o >>= 1) mx = fmaxf(mx, __shfl_xor_sync(0xffffffffu, mx, o));
    if (lane == 0) red[warp] = mx;
    __syncthreads();
    mx = red[0];
    #pragma unroll
    for (int i = 1; i < 8; i++) mx = fmaxf(mx, red[i]);
    float sum = 0.f;
    #pragma unroll
    for (int i = 0; i < 4; i++) sum += expf(v[i] - mx);
    #pragma unroll
    for (int o = 16; o > 0; o >>= 1) sum += __shfl_xor_sync(0xffffffffu, sum, o);
    if (lane == 0) red2[warp] = sum;
    __syncthreads();
    float tot = 0.f;
    #pragma unroll
    for (int i = 0; i < 8; i++) tot += red2[i];
    float lse = mx + logf(tot);
    int b = bh >> 4, h = bh & 15;
    #pragma unroll
    for (int i = 0; i < 4; i++) {
        int l = tid + 256*i;
        g_A[((size_t)b*Ll + l)*Hh + h] = v[i] - lse;
    }
}

// ---------------- Kernel 5: mma.sync fp16-split V GEMM + epilogue ----------------
// CTA 128x128, 8 warps (2M x 4N), warp tile 64x32. K chunk 32, 3-stage cp.async.
#define RS 80                        // smem row stride (bytes): 5*16 -> conflict-free ldmatrix
#define TILE_B (128*RS)              // 10240
#define OFF_AH 0
#define OFF_AL TILE_B
#define OFF_BH (2*TILE_B)
#define OFF_BL (3*TILE_B)
#define ST (4*TILE_B)                // 40960 per stage
#define VG_SMEM (3*ST)               // 122880
#define NCHUNK 32

__global__ void __launch_bounds__(256, 1) k_vgemm_mma(
    const float* __restrict__ x, const float* __restrict__ bv, float* __restrict__ out)
{
    extern __shared__ __align__(128) char smem[];
    uint32_t smem_u = smem_to_u32(smem);
    int tid = threadIdx.x;
    int lane = tid & 31, wid = tid >> 5;
    int warpM = wid >> 2, warpN = wid & 3;
    int m_base = warpM * 64, n_base = warpN * 32;
    int ntile = blockIdx.x;          // 0..7
    int mtile = blockIdx.y;          // 0..255
    int row0 = mtile * 128;
    int col0 = ntile * 128;

    float acc[4][4][4];
    #pragma unroll
    for (int mf = 0; mf < 4; mf++)
        #pragma unroll
        for (int nf = 0; nf < 4; nf++)
            #pragma unroll
            for (int r = 0; r < 4; r++) acc[mf][nf][r] = 0.f;

    auto issue_chunk = [&](int c) {
        uint32_t sb = smem_u + (c % 3) * ST;
        int k0 = c * 32;
        #pragma unroll
        for (int j = 0; j < 2; j++) {
            int i = tid + 256*j;
            int r = i >> 2, gg = i & 3;
            size_t ga = (size_t)(row0 + r)*Dd + k0 + gg*8;
            uint32_t sa = sb + r*RS + gg*16;
            cp16(sa + OFF_AH, g_Xh + ga);
            cp16(sa + OFF_AL, g_Xl + ga);
            size_t gbo = (size_t)(col0 + r)*Dd + k0 + gg*8;
            cp16(sa + OFF_BH, g_Wth + gbo);
            cp16(sa + OFF_BL, g_Wtl + gbo);
        }
        CP_COMMIT();
    };

    issue_chunk(0);
    issue_chunk(1);

    for (int c = 0; c < NCHUNK; c++) {
        if (c + 2 < NCHUNK) issue_chunk(c + 2);
        int rem = NCHUNK - 1 - c;
        if (rem >= 2)      CP_WAIT(2);
        else if (rem == 1) CP_WAIT(1);
        else               CP_WAIT(0);
        __syncthreads();

        uint32_t sb = smem_u + (c % 3) * ST;
        int arow = lane & 15;
        int brow = (lane & 7) + ((lane >> 4) << 3);
        #pragma unroll
        for (int ks = 0; ks < 2; ks++) {
            int agr = ks*2 + (lane >> 4);
            int bgr = ks*2 + ((lane >> 3) & 1);
            uint32_t Ah[4][4], Al[4][4];
            #pragma unroll
            for (int mf = 0; mf < 4; mf++) {
                uint32_t ad = sb + (m_base + mf*16 + arow)*RS + agr*16;
                LDM4(Ah[mf], ad + OFF_AH);
                LDM4(Al[mf], ad + OFF_AL);
            }
            uint32_t Bh[4][2], Bl[4][2];
            #pragma unroll
            for (int nn = 0; nn < 2; nn++) {
                uint32_t bd = sb + (n_base + nn*16 + brow)*RS + bgr*16;
                uint32_t r0, r1, r2, r3;
                asm volatile("ldmatrix.sync.aligned.m8n8.x4.shared.b16 {%0,%1,%2,%3}, [%4];"
                    : "=r"(r0), "=r"(r1), "=r"(r2), "=r"(r3) : "r"(bd + OFF_BH));
                Bh[2*nn][0] = r0; Bh[2*nn][1] = r1; Bh[2*nn+1][0] = r2; Bh[2*nn+1][1] = r3;
                asm volatile("ldmatrix.sync.aligned.m8n8.x4.shared.b16 {%0,%1,%2,%3}, [%4];"
                    : "=r"(r0), "=r"(r1), "=r"(r2), "=r"(r3) : "r"(bd + OFF_BL));
                Bl[2*nn][0] = r0; Bl[2*nn][1] = r1; Bl[2*nn+1][0] = r2; Bl[2*nn+1][1] = r3;
            }
            #pragma unroll
            for (int mf = 0; mf < 4; mf++)
                #pragma unroll
                for (int nf = 0; nf < 4; nf++) {
                    MMA(acc[mf][nf], Ah[mf], Bh[nf]);
                    MMA(acc[mf][nf], Ah[mf], Bl[nf]);
                    MMA(acc[mf][nf], Al[mf], Bh[nf]);
                }
        }
        __syncthreads();
    }

    // ---- epilogue: out = a*(acc+bv) + x (pre-LN) ----
    int g = lane >> 2, cq = lane & 3;
    int hwarp = (col0 + n_base) >> 6;     // head constant per warp (32 <= 64)
    float aval[4][2];
    #pragma unroll
    for (int mf = 0; mf < 4; mf++)
        #pragma unroll
        for (int p = 0; p < 2; p++) {
            int row = row0 + m_base + mf*16 + g + p*8;
            int l = row & (Ll - 1), b = row >> 10;
            float rate = (float)(Ll - l - 1) * (1.0f/Ll) + 1.0f;
            aval[mf][p] = g_A[((size_t)b*Ll + l)*Hh + hwarp] * rate;
        }
    float2 bvv[4];
    #pragma unroll
    for (int nf = 0; nf < 4; nf++)
        bvv[nf] = *(const float2*)(bv + col0 + n_base + nf*8 + cq*2);

    #pragma unroll
    for (int mf = 0; mf < 4; mf++)
        #pragma unroll
        for (int p = 0; p < 2; p++) {
            int row = row0 + m_base + mf*16 + g + p*8;
            float a = aval[mf][p];
            #pragma unroll
            for (int nf = 0; nf < 4; nf++) {
                size_t o = (size_t)row*Dd + col0 + n_base + nf*8 + cq*2;
                float2 xr = *(const float2*)(x + o);
                float2 r;
                r.x = a*(acc[mf][nf][p*2]     + bvv[nf].x) + xr.x;
                r.y = a*(acc[mf][nf][p*2 + 1] + bvv[nf].y) + xr.y;
                *(float2*)(out + o) = r;
            }
        }
}

// ---------------- Kernel 6: in-place LayerNorm ----------------
__global__ void k_ln(float* __restrict__ out, const float* __restrict__ gamma,
                     const float* __restrict__ beta) {
    int row = blockIdx.x;
    float4* o4 = (float4*)(out + (size_t)row*Dd);
    int tid = threadIdx.x, lane = tid & 31, warp = tid >> 5;
    __shared__ float rs[8], rq[8];
    float4 v = o4[tid];
    float s = v.x + v.y + v.z + v.w;
    float q = v.x*v.x + v.y*v.y + v.z*v.z + v.w*v.w;
    #pragma unroll
    for (int o = 16; o > 0; o >>= 1) {
        s += __shfl_xor_sync(0xffffffffu, s, o);
        q += __shfl_xor_sync(0xffffffffu, q, o);
    }
    if (lane == 0) { rs[warp] = s; rq[warp] = q; }
    __syncthreads();
    s = 0.f; q = 0.f;
    #pragma unroll
    for (int i = 0; i < 8; i++) { s += rs[i]; q += rq[i]; }
    float mean = s * (1.0f/1024.0f);
    float var  = q * (1.0f/1024.0f) - mean*mean;
    float rstd = rsqrtf(var + 1e-5f);
    float4 gm = ((const float4*)gamma)[tid];
    float4 bb = ((const float4*)beta)[tid];
    v.x = (v.x - mean)*rstd*gm.x + bb.x;
    v.y = (v.y - mean)*rstd*gm.y + bb.y;
    v.z = (v.z - mean)*rstd*gm.z + bb.z;
    v.w = (v.w - mean)*rstd*gm.w + bb.w;
    o4[tid] = v;
}

extern "C" void kernel_launch(void* const* d_in, const int* in_sizes, int n_in,
                              void* d_out, int out_size) {
    const float* x     = (const float*)d_in[0];
    const float* wq    = (const float*)d_in[1];
    const float* bq    = (const float*)d_in[2];
    const float* wk    = (const float*)d_in[3];
    const float* bk    = (const float*)d_in[4];
    const float* wv    = (const float*)d_in[5];
    const float* bv    = (const float*)d_in[6];
    const float* gamma = (const float*)d_in[7];
    const float* beta  = (const float*)d_in[8];
    float* out = (float*)d_out;

    k_split_x<<<32768, 256>>>(x);
    k_split_wT<<<dim3(32, 32), dim3(32, 8)>>>(wv);
    k_q<<<dim3(Bb, 8), 128>>>(x, wq, bq);
    k_G<<<dim3(Bb, 128), 256>>>(wk);
    k_c<<<2, 256>>>(bk);
    k_scores<<<dim3(Bb, 8), 128>>>(x);
    k_lsm<<<Bb*Hh, 256>>>();

    cudaFuncSetAttribute(k_vgemm_mma, cudaFuncAttributeMaxDynamicSharedMemorySize, VG_SMEM);
    k_vgemm_mma<<<dim3(8, 256), 256, VG_SMEM>>>(x, bv, out);

    k_ln<<<Bb*Ll, 256>>>(out, gamma, beta);
}

// round 7
// speedup vs baseline: 3.5006x; 1.2275x over previous
#include <cuda_runtime.h>
#include <cuda_fp16.h>
#include <cstdint>

#define Bb 32
#define Ll 1024
#define Dd 1024
#define Hh 16
#define DVv 64

// ---------------- device-global scratch ----------------
__device__ float g_q[Bb*Dd];
__device__ float g_G[Bb*Dd*Hh];
__device__ float g_c[Bb*Hh];
__device__ float g_S[Bb*Hh*Ll];
__device__ float g_A[Bb*Ll*Hh];
__device__ __half g_Xh[(size_t)Bb*Ll*Dd];   // 64 MB
__device__ __half g_Wth[(size_t)Dd*Dd];     // Wv^T hi  [n][k]
__device__ __half g_Wtl[(size_t)Dd*Dd];     // Wv^T lo  [n][k]

__device__ __forceinline__ uint32_t smem_to_u32(const void* p) {
    uint32_t a;
    asm("{ .reg .u64 t; cvta.to.shared.u64 t, %1; cvt.u32.u64 %0, t; }" : "=r"(a) : "l"(p));
    return a;
}
__device__ __forceinline__ void cp16(uint32_t saddr, const void* g) {
    asm volatile("cp.async.cg.shared.global [%0], [%1], 16;" :: "r"(saddr), "l"(g));
}
#define CP_COMMIT() asm volatile("cp.async.commit_group;" ::: "memory")
#define CP_WAIT(n)  asm volatile("cp.async.wait_group %0;" :: "n"(n) : "memory")

#define LDM4(R, addr) \
    asm volatile("ldmatrix.sync.aligned.m8n8.x4.shared.b16 {%0,%1,%2,%3}, [%4];" \
        : "=r"((R)[0]), "=r"((R)[1]), "=r"((R)[2]), "=r"((R)[3]) : "r"(addr))

#define MMA(D, A, B) \
    asm volatile("mma.sync.aligned.m16n8k16.row.col.f32.f16.f16.f32 " \
        "{%0,%1,%2,%3},{%4,%5,%6,%7},{%8,%9},{%0,%1,%2,%3};" \
        : "+f"((D)[0]), "+f"((D)[1]), "+f"((D)[2]), "+f"((D)[3]) \
        : "r"((A)[0]), "r"((A)[1]), "r"((A)[2]), "r"((A)[3]), "r"((B)[0]), "r"((B)[1]))

// ---------------- prep: X -> fp16 (hi only) ----------------
__global__ void k_split_x(const float* __restrict__ x) {
    size_t i = (size_t)blockIdx.x * 256 + threadIdx.x;   // float4 index
    float4 v = ((const float4*)x)[i];
    __half h0 = __float2half(v.x), h1 = __float2half(v.y);
    __half h2 = __float2half(v.z), h3 = __float2half(v.w);
    uint2 uh;
    uh.x = ((uint32_t)__half_as_ushort(h1) << 16) | __half_as_ushort(h0);
    uh.y = ((uint32_t)__half_as_ushort(h3) << 16) | __half_as_ushort(h2);
    ((uint2*)g_Xh)[i] = uh;
}

// ---------------- prep: transpose + split Wv ----------------
__global__ void k_split_wT(const float* __restrict__ wv) {
    __shared__ float t[32][33];
    int k0 = blockIdx.y * 32, n0 = blockIdx.x * 32;
    int tx = threadIdx.x, ty = threadIdx.y;   // (32, 8)
    #pragma unroll
    for (int j = 0; j < 32; j += 8)
        t[ty + j][tx] = wv[(size_t)(k0 + ty + j) * Dd + n0 + tx];
    __syncthreads();
    #pragma unroll
    for (int j = 0; j < 32; j += 8) {
        float v = t[tx][ty + j];
        __half h = __float2half(v);
        size_t o = (size_t)(n0 + ty + j) * Dd + k0 + tx;
        g_Wth[o] = h;
        g_Wtl[o] = __float2half(v - __half2float(h));
    }
}

// ---------------- Kernel 1: q = x[:, -1, :] @ wq + bq ----------------
__global__ void k_q(const float* __restrict__ x, const float* __restrict__ wq,
                    const float* __restrict__ bq) {
    __shared__ float xs[Dd];
    int b = blockIdx.x, jc = blockIdx.y;
    const float* xr = x + ((size_t)b*Ll + (Ll-1))*Dd;
    for (int i = threadIdx.x; i < Dd; i += 128) xs[i] = xr[i];
    __syncthreads();
    int j = jc*128 + threadIdx.x;
    float acc = bq[j];
    #pragma unroll 4
    for (int d = 0; d < Dd; d++) acc += xs[d] * wq[(size_t)d*Dd + j];
    g_q[b*Dd + j] = acc;
}

// ---------------- Kernel 2: G[b][din][h] ----------------
__global__ void k_G(const float* __restrict__ wk) {
    __shared__ float qs[Dd];
    int b = blockIdx.x;
    for (int i = threadIdx.x; i < Dd; i += 256) qs[i] = g_q[b*Dd + i];
    __syncthreads();
    int warp = threadIdx.x >> 5, lane = threadIdx.x & 31;
    int din = blockIdx.y*8 + warp;
    const float* wrow = wk + (size_t)din*Dd;
    float mine = 0.f;
    #pragma unroll 4
    for (int k = 0; k < 32; k++) {
        int j = k*32 + lane;
        float p = wrow[j] * qs[j];
        #pragma unroll
        for (int o = 16; o > 0; o >>= 1) p += __shfl_xor_sync(0xffffffffu, p, o);
        if (lane == (k >> 1)) mine += p;
    }
    if (lane < Hh) g_G[((size_t)b*Dd + din)*Hh + lane] = mine;
}

// ---------------- Kernel 2b ----------------
__global__ void k_c(const float* __restrict__ bk) {
    int t = blockIdx.x*blockDim.x + threadIdx.x;
    if (t >= Bb*Hh) return;
    int b = t >> 4, h = t & 15;
    float acc = 0.f;
    #pragma unroll 8
    for (int dv = 0; dv < DVv; dv++) {
        int j = h*DVv + dv;
        acc += bk[j] * g_q[b*Dd + j];
    }
    g_c[t] = acc;
}

// ---------------- Kernel 3: scores (register-tiled) ----------------
__global__ void __launch_bounds__(128) k_scores(const float* __restrict__ x) {
    __shared__ __align__(16) float Xs[128][68];
    __shared__ __align__(16) float Gs[16][72];
    int b = blockIdx.x, lt = blockIdx.y;
    int l0 = lt * 128;
    int tid = threadIdx.x;
    int tx = tid & 7, ty = tid >> 3;
    float acc[8][2];
    #pragma unroll
    for (int j = 0; j < 8; j++) { acc[j][0] = 0.f; acc[j][1] = 0.f; }
    const float* xb = x + ((size_t)b*Ll + l0)*Dd;
    const float* gb = g_G + (size_t)b*Dd*Hh;

    for (int k0 = 0; k0 < Dd; k0 += 64) {
        #pragma unroll
        for (int it = 0; it < 16; it++) {
            int i = tid + 128*it;
            int row = i >> 4, ks = i & 15;
            ((float4*)&Xs[row][0])[ks] = ((const float4*)(xb + (size_t)row*Dd + k0))[ks];
        }
        #pragma unroll
        for (int it = 0; it < 8; it++) {
            int e = tid + 128*it;
            int din = e >> 4, h = e & 15;
            Gs[h][din] = gb[(size_t)(k0 + din)*Hh + h];
        }
        __syncthreads();
        #pragma unroll
        for (int k4 = 0; k4 < 16; k4++) {
            float4 g0 = ((float4*)&Gs[2*tx][0])[k4];
            float4 g1 = ((float4*)&Gs[2*tx+1][0])[k4];
            #pragma unroll
            for (int j = 0; j < 8; j++) {
                float4 xv = ((float4*)&Xs[ty + 16*j][0])[k4];
                acc[j][0] += xv.x*g0.x + xv.y*g0.y + xv.z*g0.z + xv.w*g0.w;
                acc[j][1] += xv.x*g1.x + xv.y*g1.y + xv.z*g1.z + xv.w*g1.w;
            }
        }
        __syncthreads();
    }
    float invtemp = 1.0f / (32.0f + 1e-5f);
    float c0 = g_c[b*Hh + 2*tx], c1 = g_c[b*Hh + 2*tx + 1];
    #pragma unroll
    for (int j = 0; j < 8; j++) {
        int l = l0 + ty + 16*j;
        float rate = (float)(Ll - l - 1) * (1.0f/Ll) + 1.0f;
        g_S[((size_t)b*Hh + 2*tx)*Ll + l]     = rate * (acc[j][0] + c0) * invtemp;
        g_S[((size_t)b*Hh + 2*tx + 1)*Ll + l] = rate * (acc[j][1] + c1) * invtemp;
    }
}

// ---------------- Kernel 4: log-softmax ----------------
__global__ void k_lsm() {
    int bh = blockIdx.x;
    const float* s = g_S + (size_t)bh*Ll;
    __shared__ float red[8], red2[8];
    int tid = threadIdx.x, lane = tid & 31, warp = tid >> 5;
    float v[4]; float mx = -3.4e38f;
    #pragma unroll
    for (int i = 0; i < 4; i++) { v[i] = s[tid + 256*i]; mx = fmaxf(mx, v[i]); }
    #pragma unroll
    for (int o = 16; o > 0; o >>= 1) mx = fmaxf(mx, __shfl_xor_sync(0xffffffffu, mx, o));
    if (lane == 0) red[warp] = mx;
    __syncthreads();
    mx = red[0];
    #pragma unroll
    for (int i = 1; i < 8; i++) mx = fmaxf(mx, red[i]);
    float sum = 0.f;
    #pragma unroll
    for (int i = 0; i < 4; i++) sum += expf(v[i] - mx);
    #pragma unroll
    for (int o = 16; o > 0; o >>= 1) sum += __shfl_xor_sync(0xffffffffu, sum, o);
    if (lane == 0) red2[warp] = sum;
    __syncthreads();
    float tot = 0.f;
    #pragma unroll
    for (int i = 0; i < 8; i++) tot += red2[i];
    float lse = mx + logf(tot);
    int b = bh >> 4, h = bh & 15;
    #pragma unroll
    for (int i = 0; i < 4; i++) {
        int l = tid + 256*i;
        g_A[((size_t)b*Ll + l)*Hh + h] = v[i] - lse;
    }
}

// ---------------- Kernel 5: mma.sync 2-pass fp16 V GEMM + epilogue ----------------
// CTA 128x128, 8 warps (2M x 4N), warp tile 64x32. K chunk 32, 4-stage cp.async.
#define RS 80                        // smem row stride (bytes): 5*16 -> conflict-free ldmatrix
#define TILE_B (128*RS)              // 10240
#define OFF_AH 0
#define OFF_BH TILE_B
#define OFF_BL (2*TILE_B)
#define ST (3*TILE_B)                // 30720 per stage
#define VG_SMEM (4*ST)               // 122880
#define NCHUNK 32

__global__ void __launch_bounds__(256, 1) k_vgemm_mma(
    const float* __restrict__ x, const float* __restrict__ bv, float* __restrict__ out)
{
    extern __shared__ __align__(128) char smem[];
    uint32_t smem_u = smem_to_u32(smem);
    int tid = threadIdx.x;
    int lane = tid & 31, wid = tid >> 5;
    int warpM = wid >> 2, warpN = wid & 3;
    int m_base = warpM * 64, n_base = warpN * 32;
    int ntile = blockIdx.x;          // 0..7
    int mtile = blockIdx.y;          // 0..255
    int row0 = mtile * 128;
    int col0 = ntile * 128;

    float acc[4][4][4];
    #pragma unroll
    for (int mf = 0; mf < 4; mf++)
        #pragma unroll
        for (int nf = 0; nf < 4; nf++)
            #pragma unroll
            for (int r = 0; r < 4; r++) acc[mf][nf][r] = 0.f;

    auto issue_chunk = [&](int c) {
        uint32_t sb = smem_u + (c & 3) * ST;
        int k0 = c * 32;
        #pragma unroll
        for (int j = 0; j < 2; j++) {
            int i = tid + 256*j;
            int r = i >> 2, gg = i & 3;
            size_t ga = (size_t)(row0 + r)*Dd + k0 + gg*8;
            uint32_t sa = sb + r*RS + gg*16;
            cp16(sa + OFF_AH, g_Xh + ga);
            size_t gbo = (size_t)(col0 + r)*Dd + k0 + gg*8;
            cp16(sa + OFF_BH, g_Wth + gbo);
            cp16(sa + OFF_BL, g_Wtl + gbo);
        }
        CP_COMMIT();
    };

    issue_chunk(0);
    issue_chunk(1);
    issue_chunk(2);

    for (int c = 0; c < NCHUNK; c++) {
        if (c + 3 < NCHUNK) issue_chunk(c + 3);
        int rem = NCHUNK - 1 - c;
        if (rem >= 3)      CP_WAIT(3);
        else if (rem == 2) CP_WAIT(2);
        else if (rem == 1) CP_WAIT(1);
        else               CP_WAIT(0);
        __syncthreads();

        uint32_t sb = smem_u + (c & 3) * ST;
        int arow = lane & 15;
        int brow = (lane & 7) + ((lane >> 4) << 3);
        #pragma unroll
        for (int ks = 0; ks < 2; ks++) {
            int agr = ks*2 + (lane >> 4);
            int bgr = ks*2 + ((lane >> 3) & 1);
            uint32_t Ah[4][4];
            #pragma unroll
            for (int mf = 0; mf < 4; mf++) {
                uint32_t ad = sb + (m_base + mf*16 + arow)*RS + agr*16;
                LDM4(Ah[mf], ad + OFF_AH);
            }
            uint32_t Bh[4][2], Bl[4][2];
            #pragma unroll
            for (int nn = 0; nn < 2; nn++) {
                uint32_t bd = sb + (n_base + nn*16 + brow)*RS + bgr*16;
                uint32_t r0, r1, r2, r3;
                asm volatile("ldmatrix.sync.aligned.m8n8.x4.shared.b16 {%0,%1,%2,%3}, [%4];"
                    : "=r"(r0), "=r"(r1), "=r"(r2), "=r"(r3) : "r"(bd + OFF_BH));
                Bh[2*nn][0] = r0; Bh[2*nn][1] = r1; Bh[2*nn+1][0] = r2; Bh[2*nn+1][1] = r3;
                asm volatile("ldmatrix.sync.aligned.m8n8.x4.shared.b16 {%0,%1,%2,%3}, [%4];"
                    : "=r"(r0), "=r"(r1), "=r"(r2), "=r"(r3) : "r"(bd + OFF_BL));
                Bl[2*nn][0] = r0; Bl[2*nn][1] = r1; Bl[2*nn+1][0] = r2; Bl[2*nn+1][1] = r3;
            }
            #pragma unroll
            for (int mf = 0; mf < 4; mf++)
                #pragma unroll
                for (int nf = 0; nf < 4; nf++) {
                    MMA(acc[mf][nf], Ah[mf], Bh[nf]);
                    MMA(acc[mf][nf], Ah[mf], Bl[nf]);
                }
        }
        __syncthreads();
    }

    // ---- epilogue: out = a*(acc+bv) + x (pre-LN) ----
    int g = lane >> 2, cq = lane & 3;
    int hwarp = (col0 + n_base) >> 6;     // head constant per warp (32 <= 64)
    float aval[4][2];
    #pragma unroll
    for (int mf = 0; mf < 4; mf++)
        #pragma unroll
        for (int p = 0; p < 2; p++) {
            int row = row0 + m_base + mf*16 + g + p*8;
            int l = row & (Ll - 1), b = row >> 10;
            float rate = (float)(Ll - l - 1) * (1.0f/Ll) + 1.0f;
            aval[mf][p] = g_A[((size_t)b*Ll + l)*Hh + hwarp] * rate;
        }
    float2 bvv[4];
    #pragma unroll
    for (int nf = 0; nf < 4; nf++)
        bvv[nf] = *(const float2*)(bv + col0 + n_base + nf*8 + cq*2);

    #pragma unroll
    for (int mf = 0; mf < 4; mf++)
        #pragma unroll
        for (int p = 0; p < 2; p++) {
            int row = row0 + m_base + mf*16 + g + p*8;
            float a = aval[mf][p];
            #pragma unroll
            for (int nf = 0; nf < 4; nf++) {
                size_t o = (size_t)row*Dd + col0 + n_base + nf*8 + cq*2;
                float2 xr = *(const float2*)(x + o);
                float2 r;
                r.x = a*(acc[mf][nf][p*2]     + bvv[nf].x) + xr.x;
                r.y = a*(acc[mf][nf][p*2 + 1] + bvv[nf].y) + xr.y;
                *(float2*)(out + o) = r;
            }
        }
}

// ---------------- Kernel 6: in-place LayerNorm ----------------
__global__ void k_ln(float* __restrict__ out, const float* __restrict__ gamma,
                     const float* __restrict__ beta) {
    int row = blockIdx.x;
    float4* o4 = (float4*)(out + (size_t)row*Dd);
    int tid = threadIdx.x, lane = tid & 31, warp = tid >> 5;
    __shared__ float rs[8], rq[8];
    float4 v = o4[tid];
    float s = v.x + v.y + v.z + v.w;
    float q = v.x*v.x + v.y*v.y + v.z*v.z + v.w*v.w;
    #pragma unroll
    for (int o = 16; o > 0; o >>= 1) {
        s += __shfl_xor_sync(0xffffffffu, s, o);
        q += __shfl_xor_sync(0xffffffffu, q, o);
    }
    if (lane == 0) { rs[warp] = s; rq[warp] = q; }
    __syncthreads();
    s = 0.f; q = 0.f;
    #pragma unroll
    for (int i = 0; i < 8; i++) { s += rs[i]; q += rq[i]; }
    float mean = s * (1.0f/1024.0f);
    float var  = q * (1.0f/1024.0f) - mean*mean;
    float rstd = rsqrtf(var + 1e-5f);
    float4 gm = ((const float4*)gamma)[tid];
    float4 bb = ((const float4*)beta)[tid];
    v.x = (v.x - mean)*rstd*gm.x + bb.x;
    v.y = (v.y - mean)*rstd*gm.y + bb.y;
    v.z = (v.z - mean)*rstd*gm.z + bb.z;
    v.w = (v.w - mean)*rstd*gm.w + bb.w;
    o4[tid] = v;
}

extern "C" void kernel_launch(void* const* d_in, const int* in_sizes, int n_in,
                              void* d_out, int out_size) {
    const float* x     = (const float*)d_in[0];
    const float* wq    = (const float*)d_in[1];
    const float* bq    = (const float*)d_in[2];
    const float* wk    = (const float*)d_in[3];
    const float* bk    = (const float*)d_in[4];
    const float* wv    = (const float*)d_in[5];
    const float* bv    = (const float*)d_in[6];
    const float* gamma = (const float*)d_in[7];
    const float* beta  = (const float*)d_in[8];
    float* out = (float*)d_out;

    k_split_x<<<32768, 256>>>(x);
    k_split_wT<<<dim3(32, 32), dim3(32, 8)>>>(wv);
    k_q<<<dim3(Bb, 8), 128>>>(x, wq, bq);
    k_G<<<dim3(Bb, 128), 256>>>(wk);
    k_c<<<2, 256>>>(bk);
    k_scores<<<dim3(Bb, 8), 128>>>(x);
    k_lsm<<<Bb*Hh, 256>>>();

    cudaFuncSetAttribute(k_vgemm_mma, cudaFuncAttributeMaxDynamicSharedMemorySize, VG_SMEM);
    k_vgemm_mma<<<dim3(8, 256), 256, VG_SMEM>>>(x, bv, out);

    k_ln<<<Bb*Ll, 256>>>(out, gamma, beta);
}

// round 9
// speedup vs baseline: 3.8544x; 1.1011x over previous
#include <cuda_runtime.h>
#include <cuda_fp16.h>
#include <cstdint>

#define Bb 32
#define Ll 1024
#define Dd 1024
#define Hh 16
#define DVv 64

// ---------------- device-global scratch ----------------
__device__ float g_q[Bb*Dd];
__device__ float g_G[Bb*Hh*Dd];             // [b][h][din]
__device__ float g_c[Bb*Hh];
__device__ float g_S[Bb*Hh*Ll];
__device__ float g_A[Bb*Ll*Hh];
__device__ __half g_Xh[(size_t)Bb*Ll*Dd];   // 64 MB
__device__ __half g_Wth[(size_t)Dd*Dd];     // Wv^T hi  [n][k]
__device__ __half g_Wtl[(size_t)Dd*Dd];     // Wv^T lo  [n][k]

__device__ __forceinline__ uint32_t smem_to_u32(const void* p) {
    uint32_t a;
    asm("{ .reg .u64 t; cvta.to.shared.u64 t, %1; cvt.u32.u64 %0, t; }" : "=r"(a) : "l"(p));
    return a;
}
__device__ __forceinline__ void cp16(uint32_t saddr, const void* g) {
    asm volatile("cp.async.cg.shared.global [%0], [%1], 16;" :: "r"(saddr), "l"(g));
}
#define CP_COMMIT() asm volatile("cp.async.commit_group;" ::: "memory")
#define CP_WAIT(n)  asm volatile("cp.async.wait_group %0;" :: "n"(n) : "memory")

#define LDM4(R, addr) \
    asm volatile("ldmatrix.sync.aligned.m8n8.x4.shared.b16 {%0,%1,%2,%3}, [%4];" \
        : "=r"((R)[0]), "=r"((R)[1]), "=r"((R)[2]), "=r"((R)[3]) : "r"(addr))

#define MMA(D, A, B) \
    asm volatile("mma.sync.aligned.m16n8k16.row.col.f32.f16.f16.f32 " \
        "{%0,%1,%2,%3},{%4,%5,%6,%7},{%8,%9},{%0,%1,%2,%3};" \
        : "+f"((D)[0]), "+f"((D)[1]), "+f"((D)[2]), "+f"((D)[3]) \
        : "r"((A)[0]), "r"((A)[1]), "r"((A)[2]), "r"((A)[3]), "r"((B)[0]), "r"((B)[1]))

// ---------------- prep: X -> fp16 (hi only) ----------------
__global__ void k_split_x(const float* __restrict__ x) {
    size_t i = (size_t)blockIdx.x * 256 + threadIdx.x;   // float4 index
    float4 v = ((const float4*)x)[i];
    __half h0 = __float2half(v.x), h1 = __float2half(v.y);
    __half h2 = __float2half(v.z), h3 = __float2half(v.w);
    uint2 uh;
    uh.x = ((uint32_t)__half_as_ushort(h1) << 16) | __half_as_ushort(h0);
    uh.y = ((uint32_t)__half_as_ushort(h3) << 16) | __half_as_ushort(h2);
    ((uint2*)g_Xh)[i] = uh;
}

// ---------------- prep: transpose + split Wv ----------------
__global__ void k_split_wT(const float* __restrict__ wv) {
    __shared__ float t[32][33];
    int k0 = blockIdx.y * 32, n0 = blockIdx.x * 32;
    int tx = threadIdx.x, ty = threadIdx.y;   // (32, 8)
    #pragma unroll
    for (int j = 0; j < 32; j += 8)
        t[ty + j][tx] = wv[(size_t)(k0 + ty + j) * Dd + n0 + tx];
    __syncthreads();
    #pragma unroll
    for (int j = 0; j < 32; j += 8) {
        float v = t[tx][ty + j];
        __half h = __float2half(v);
        size_t o = (size_t)(n0 + ty + j) * Dd + k0 + tx;
        g_Wth[o] = h;
        g_Wtl[o] = __float2half(v - __half2float(h));
    }
}

// ---------------- Kernel 1: q = x[:, -1, :] @ wq + bq ----------------
__global__ void k_q(const float* __restrict__ x, const float* __restrict__ wq,
                    const float* __restrict__ bq) {
    __shared__ float xs[Dd];
    int b = blockIdx.x, jc = blockIdx.y;
    const float* xr = x + ((size_t)b*Ll + (Ll-1))*Dd;
    for (int i = threadIdx.x; i < Dd; i += 128) xs[i] = xr[i];
    __syncthreads();
    int j = jc*128 + threadIdx.x;
    float acc = bq[j];
    #pragma unroll 4
    for (int d = 0; d < Dd; d++) acc += xs[d] * wq[(size_t)d*Dd + j];
    g_q[b*Dd + j] = acc;
}

// ---------------- Kernel 2: G[b][h][din] = sum_dv wk[din][h*64+dv]*q[b][h*64+dv] ----------------
__global__ void __launch_bounds__(256) k_G(const float* __restrict__ wk) {
    __shared__ float qs[32][64];       // q[b][h*64+dv]
    __shared__ float wks[64][128];     // wks[dv][din_local]  (transposed)
    int h = blockIdx.x, dg = blockIdx.y;   // grid (16, 8)
    int tid = threadIdx.x;
    int din0 = dg * 128;

    for (int i = tid; i < 512; i += 256) {            // 32 b x 16 float4
        int b = i >> 4, d4 = i & 15;
        ((float4*)&qs[b][0])[d4] = *(const float4*)&g_q[b*Dd + h*64 + d4*4];
    }
    for (int it = 0; it < 8; it++) {                  // 128 rows x 16 float4
        int i = tid + 256*it;
        int r = i >> 4, k4 = i & 15;
        float4 w = *(const float4*)&wk[(size_t)(din0 + r)*Dd + h*64 + k4*4];
        wks[k4*4 + 0][r] = w.x;
        wks[k4*4 + 1][r] = w.y;
        wks[k4*4 + 2][r] = w.z;
        wks[k4*4 + 3][r] = w.w;
    }
    __syncthreads();

    int dl = tid & 127, bg = tid >> 7;                // din local, batch half
    float acc[16];
    #pragma unroll
    for (int bi = 0; bi < 16; bi++) acc[bi] = 0.f;
    #pragma unroll 4
    for (int k = 0; k < 64; k++) {
        float wv = wks[k][dl];
        #pragma unroll
        for (int bi = 0; bi < 16; bi++)
            acc[bi] += wv * qs[bg*16 + bi][k];
    }
    #pragma unroll
    for (int bi = 0; bi < 16; bi++) {
        int b = bg*16 + bi;
        g_G[((size_t)b*Hh + h)*Dd + din0 + dl] = acc[bi];
    }
}

// ---------------- Kernel 2b ----------------
__global__ void k_c(const float* __restrict__ bk) {
    int t = blockIdx.x*blockDim.x + threadIdx.x;
    if (t >= Bb*Hh) return;
    int b = t >> 4, h = t & 15;
    float acc = 0.f;
    #pragma unroll 8
    for (int dv = 0; dv < DVv; dv++) {
        int j = h*DVv + dv;
        acc += bk[j] * g_q[b*Dd + j];
    }
    g_c[t] = acc;
}

// ---------------- Kernel 3: scores (register-tiled) ----------------
__global__ void __launch_bounds__(128) k_scores(const float* __restrict__ x) {
    __shared__ __align__(16) float Xs[128][68];
    __shared__ __align__(16) float Gs[16][72];
    int b = blockIdx.x, lt = blockIdx.y;
    int l0 = lt * 128;
    int tid = threadIdx.x;
    int tx = tid & 7, ty = tid >> 3;
    float acc[8][2];
    #pragma unroll
    for (int j = 0; j < 8; j++) { acc[j][0] = 0.f; acc[j][1] = 0.f; }
    const float* xb = x + ((size_t)b*Ll + l0)*Dd;
    const float* gb = g_G + (size_t)b*Hh*Dd;          // [h][din]

    for (int k0 = 0; k0 < Dd; k0 += 64) {
        #pragma unroll
        for (int it = 0; it < 16; it++) {
            int i = tid + 128*it;
            int row = i >> 4, ks = i & 15;
            ((float4*)&Xs[row][0])[ks] = ((const float4*)(xb + (size_t)row*Dd + k0))[ks];
        }
        #pragma unroll
        for (int it = 0; it < 8; it++) {
            int e = tid + 128*it;
            int h = e >> 6, dnn = e & 63;
            Gs[h][dnn] = gb[(size_t)h*Dd + k0 + dnn];
        }
        __syncthreads();
        #pragma unroll
        for (int k4 = 0; k4 < 16; k4++) {
            float4 g0 = ((float4*)&Gs[2*tx][0])[k4];
            float4 g1 = ((float4*)&Gs[2*tx+1][0])[k4];
            #pragma unroll
            for (int j = 0; j < 8; j++) {
                float4 xv = ((float4*)&Xs[ty + 16*j][0])[k4];
                acc[j][0] += xv.x*g0.x + xv.y*g0.y + xv.z*g0.z + xv.w*g0.w;
                acc[j][1] += xv.x*g1.x + xv.y*g1.y + xv.z*g1.z + xv.w*g1.w;
            }
        }
        __syncthreads();
    }
    float invtemp = 1.0f / (32.0f + 1e-5f);
    float c0 = g_c[b*Hh + 2*tx], c1 = g_c[b*Hh + 2*tx + 1];
    #pragma unroll
    for (int j = 0; j < 8; j++) {
        int l = l0 + ty + 16*j;
        float rate = (float)(Ll - l - 1) * (1.0f/Ll) + 1.0f;
        g_S[((size_t)b*Hh + 2*tx)*Ll + l]     = rate * (acc[j][0] + c0) * invtemp;
        g_S[((size_t)b*Hh + 2*tx + 1)*Ll + l] = rate * (acc[j][1] + c1) * invtemp;
    }
}

// ---------------- Kernel 4: log-softmax ----------------
__global__ void k_lsm() {
    int bh = blockIdx.x;
    const float* s = g_S + (size_t)bh*Ll;
    __shared__ float red[8], red2[8];
    int tid = threadIdx.x, lane = tid & 31, warp = tid >> 5;
    float v[4]; float mx = -3.4e38f;
    #pragma unroll
    for (int i = 0; i < 4; i++) { v[i] = s[tid + 256*i]; mx = fmaxf(mx, v[i]); }
    #pragma unroll
    for (int o = 16; o > 0; o >>= 1) mx = fmaxf(mx, __shfl_xor_sync(0xffffffffu, mx, o));
    if (lane == 0) red[warp] = mx;
    __syncthreads();
    mx = red[0];
    #pragma unroll
    for (int i = 1; i < 8; i++) mx = fmaxf(mx, red[i]);
    float sum = 0.f;
    #pragma unroll
    for (int i = 0; i < 4; i++) sum += expf(v[i] - mx);
    #pragma unroll
    for (int o = 16; o > 0; o >>= 1) sum += __shfl_xor_sync(0xffffffffu, sum, o);
    if (lane == 0) red2[warp] = sum;
    __syncthreads();
    float tot = 0.f;
    #pragma unroll
    for (int i = 0; i < 8; i++) tot += red2[i];
    float lse = mx + logf(tot);
    int b = bh >> 4, h = bh & 15;
    #pragma unroll
    for (int i = 0; i < 4; i++) {
        int l = tid + 256*i;
        g_A[((size_t)b*Ll + l)*Hh + h] = v[i] - lse;
    }
}

// ---------------- Kernel 5: mma.sync 2-pass fp16 V GEMM + epilogue ----------------
// CTA 128x128, 8 warps (2M x 4N), warp tile 64x32. K chunk 64, 3-stage cp.async,
// single barrier per chunk.
#define RS2 144                      // smem row stride (bytes): 9*16 -> conflict-free ldmatrix
#define ATILE (128*RS2)              // 18432
#define OFF_BH2 ATILE
#define OFF_BL2 (2*ATILE)
#define ST2 (3*ATILE)                // 55296 per stage
#define VG_SMEM (3*ST2)              // 165888
#define NCH 16

__global__ void __launch_bounds__(256, 1) k_vgemm_mma(
    const float* __restrict__ x, const float* __restrict__ bv, float* __restrict__ out)
{
    extern __shared__ __align__(128) char smem[];
    uint32_t smem_u = smem_to_u32(smem);
    int tid = threadIdx.x;
    int lane = tid & 31, wid = tid >> 5;
    int warpM = wid >> 2, warpN = wid & 3;
    int m_base = warpM * 64, n_base = warpN * 32;
    int ntile = blockIdx.x;          // 0..7
    int mtile = blockIdx.y;          // 0..255
    int row0 = mtile * 128;
    int col0 = ntile * 128;

    float acc[4][4][4];
    #pragma unroll
    for (int mf = 0; mf < 4; mf++)
        #pragma unroll
        for (int nf = 0; nf < 4; nf++)
            #pragma unroll
            for (int r = 0; r < 4; r++) acc[mf][nf][r] = 0.f;

    auto issue_chunk = [&](int c) {
        uint32_t sb = smem_u + (c % 3) * ST2;
        int k0 = c * 64;
        #pragma unroll
        for (int j = 0; j < 4; j++) {
            int i = tid + 256*j;
            int r = i >> 3, gg = i & 7;
            size_t ga = (size_t)(row0 + r)*Dd + k0 + gg*8;
            uint32_t sa = sb + r*RS2 + gg*16;
            cp16(sa, g_Xh + ga);
            size_t gbo = (size_t)(col0 + r)*Dd + k0 + gg*8;
            cp16(sa + OFF_BH2, g_Wth + gbo);
            cp16(sa + OFF_BL2, g_Wtl + gbo);
        }
        CP_COMMIT();
    };

    issue_chunk(0);
    issue_chunk(1);

    for (int c = 0; c < NCH; c++) {
        if (c == NCH - 1) { CP_WAIT(0); } else { CP_WAIT(1); }
        __syncthreads();
        if (c + 2 < NCH) issue_chunk(c + 2);

        uint32_t sb = smem_u + (c % 3) * ST2;
        int arow = lane & 15;
        int brow = (lane & 7) + ((lane >> 4) << 3);
        #pragma unroll
        for (int ks = 0; ks < 4; ks++) {
            int agr = ks*2 + (lane >> 4);
            int bgr = ks*2 + ((lane >> 3) & 1);
            uint32_t Ah[4][4];
            #pragma unroll
            for (int mf = 0; mf < 4; mf++) {
                uint32_t ad = sb + (m_base + mf*16 + arow)*RS2 + agr*16;
                LDM4(Ah[mf], ad);
            }
            uint32_t Bh[4][2], Bl[4][2];
            #pragma unroll
            for (int nn = 0; nn < 2; nn++) {
                uint32_t bd = sb + (n_base + nn*16 + brow)*RS2 + bgr*16;
                uint32_t r0, r1, r2, r3;
                asm volatile("ldmatrix.sync.aligned.m8n8.x4.shared.b16 {%0,%1,%2,%3}, [%4];"
                    : "=r"(r0), "=r"(r1), "=r"(r2), "=r"(r3) : "r"(bd + OFF_BH2));
                Bh[2*nn][0] = r0; Bh[2*nn][1] = r1; Bh[2*nn+1][0] = r2; Bh[2*nn+1][1] = r3;
                asm volatile("ldmatrix.sync.aligned.m8n8.x4.shared.b16 {%0,%1,%2,%3}, [%4];"
                    : "=r"(r0), "=r"(r1), "=r"(r2), "=r"(r3) : "r"(bd + OFF_BL2));
                Bl[2*nn][0] = r0; Bl[2*nn][1] = r1; Bl[2*nn+1][0] = r2; Bl[2*nn+1][1] = r3;
            }
            #pragma unroll
            for (int mf = 0; mf < 4; mf++)
                #pragma unroll
                for (int nf = 0; nf < 4; nf++) {
                    MMA(acc[mf][nf], Ah[mf], Bh[nf]);
                    MMA(acc[mf][nf], Ah[mf], Bl[nf]);
                }
        }
    }

    // ---- epilogue: out = a*(acc+bv) + x (pre-LN) ----
    int g = lane >> 2, cq = lane & 3;
    int hwarp = (col0 + n_base) >> 6;     // head constant per warp (32 <= 64)
    float aval[4][2];
    #pragma unroll
    for (int mf = 0; mf < 4; mf++)
        #pragma unroll
        for (int p = 0; p < 2; p++) {
            int row = row0 + m_base + mf*16 + g + p*8;
            int l = row & (Ll - 1), b = row >> 10;
            float rate = (float)(Ll - l - 1) * (1.0f/Ll) + 1.0f;
            aval[mf][p] = g_A[((size_t)b*Ll + l)*Hh + hwarp] * rate;
        }
    float2 bvv[4];
    #pragma unroll
    for (int nf = 0; nf < 4; nf++)
        bvv[nf] = *(const float2*)(bv + col0 + n_base + nf*8 + cq*2);

    #pragma unroll
    for (int mf = 0; mf < 4; mf++)
        #pragma unroll
        for (int p = 0; p < 2; p++) {
            int row = row0 + m_base + mf*16 + g + p*8;
            float a = aval[mf][p];
            #pragma unroll
            for (int nf = 0; nf < 4; nf++) {
                size_t o = (size_t)row*Dd + col0 + n_base + nf*8 + cq*2;
                float2 xr = *(const float2*)(x + o);
                float2 r;
                r.x = a*(acc[mf][nf][p*2]     + bvv[nf].x) + xr.x;
                r.y = a*(acc[mf][nf][p*2 + 1] + bvv[nf].y) + xr.y;
                *(float2*)(out + o) = r;
            }
        }
}

// ---------------- Kernel 6: in-place LayerNorm ----------------
__global__ void k_ln(float* __restrict__ out, const float* __restrict__ gamma,
                     const float* __restrict__ beta) {
    int row = blockIdx.x;
    float4* o4 = (float4*)(out + (size_t)row*Dd);
    int tid = threadIdx.x, lane = tid & 31, warp = tid >> 5;
    __shared__ float rs[8], rq[8];
    float4 v = o4[tid];
    float s = v.x + v.y + v.z + v.w;
    float q = v.x*v.x + v.y*v.y + v.z*v.z + v.w*v.w;
    #pragma unroll
    for (int o = 16; o > 0; o >>= 1) {
        s += __shfl_xor_sync(0xffffffffu, s, o);
        q += __shfl_xor_sync(0xffffffffu, q, o);
    }
    if (lane == 0) { rs[warp] = s; rq[warp] = q; }
    __syncthreads();
    s = 0.f; q = 0.f;
    #pragma unroll
    for (int i = 0; i < 8; i++) { s += rs[i]; q += rq[i]; }
    float mean = s * (1.0f/1024.0f);
    float var  = q * (1.0f/1024.0f) - mean*mean;
    float rstd = rsqrtf(var + 1e-5f);
    float4 gm = ((const float4*)gamma)[tid];
    float4 bb = ((const float4*)beta)[tid];
    v.x = (v.x - mean)*rstd*gm.x + bb.x;
    v.y = (v.y - mean)*rstd*gm.y + bb.y;
    v.z = (v.z - mean)*rstd*gm.z + bb.z;
    v.w = (v.w - mean)*rstd*gm.w + bb.w;
    o4[tid] = v;
}

extern "C" void kernel_launch(void* const* d_in, const int* in_sizes, int n_in,
                              void* d_out, int out_size) {
    const float* x     = (const float*)d_in[0];
    const float* wq    = (const float*)d_in[1];
    const float* bq    = (const float*)d_in[2];
    const float* wk    = (const float*)d_in[3];
    const float* bk    = (const float*)d_in[4];
    const float* wv    = (const float*)d_in[5];
    const float* bv    = (const float*)d_in[6];
    const float* gamma = (const float*)d_in[7];
    const float* beta  = (const float*)d_in[8];
    float* out = (float*)d_out;

    k_split_x<<<32768, 256>>>(x);
    k_split_wT<<<dim3(32, 32), dim3(32, 8)>>>(wv);
    k_q<<<dim3(Bb, 8), 128>>>(x, wq, bq);
    k_G<<<dim3(Hh, 8), 256>>>(wk);
    k_c<<<2, 256>>>(bk);
    k_scores<<<dim3(Bb, 8), 128>>>(x);
    k_lsm<<<Bb*Hh, 256>>>();

    cudaFuncSetAttribute(k_vgemm_mma, cudaFuncAttributeMaxDynamicSharedMemorySize, VG_SMEM);
    k_vgemm_mma<<<dim3(8, 256), 256, VG_SMEM>>>(x, bv, out);

    k_ln<<<Bb*Ll, 256>>>(out, gamma, beta);
}

// round 11
// speedup vs baseline: 5.2102x; 1.3517x over previous
#include <cuda_runtime.h>
#include <cuda_fp16.h>
#include <cstdint>

#define Bb 32
#define Ll 1024
#define Dd 1024
#define Hh 16
#define DVv 64

// ---------------- device-global scratch ----------------
__device__ float g_q[Bb*Dd];
__device__ float g_G[Bb*Hh*Dd];             // [b][h][din]
__device__ float g_c[Bb*Hh];
__device__ float g_S[Bb*Hh*Ll];
__device__ float g_A[Bb*Ll*Hh];
__device__ __half g_Xh[(size_t)Bb*Ll*Dd];   // 64 MB
__device__ __half g_Wth[(size_t)Dd*Dd];     // Wv^T hi  [n][k]

__device__ __forceinline__ uint32_t smem_to_u32(const void* p) {
    uint32_t a;
    asm("{ .reg .u64 t; cvta.to.shared.u64 t, %1; cvt.u32.u64 %0, t; }" : "=r"(a) : "l"(p));
    return a;
}
__device__ __forceinline__ void cp16(uint32_t saddr, const void* g) {
    asm volatile("cp.async.cg.shared.global [%0], [%1], 16;" :: "r"(saddr), "l"(g));
}
#define CP_COMMIT() asm volatile("cp.async.commit_group;" ::: "memory")
#define CP_WAIT(n)  asm volatile("cp.async.wait_group %0;" :: "n"(n) : "memory")

#define LDM4(R, addr) \
    asm volatile("ldmatrix.sync.aligned.m8n8.x4.shared.b16 {%0,%1,%2,%3}, [%4];" \
        : "=r"((R)[0]), "=r"((R)[1]), "=r"((R)[2]), "=r"((R)[3]) : "r"(addr))

#define MMA(D, A, B) \
    asm volatile("mma.sync.aligned.m16n8k16.row.col.f32.f16.f16.f32 " \
        "{%0,%1,%2,%3},{%4,%5,%6,%7},{%8,%9},{%0,%1,%2,%3};" \
        : "+f"((D)[0]), "+f"((D)[1]), "+f"((D)[2]), "+f"((D)[3]) \
        : "r"((A)[0]), "r"((A)[1]), "r"((A)[2]), "r"((A)[3]), "r"((B)[0]), "r"((B)[1]))

// ---------------- prep: X -> fp16 ----------------
__global__ void k_split_x(const float* __restrict__ x) {
    size_t i = (size_t)blockIdx.x * 256 + threadIdx.x;   // float4 index
    float4 v = ((const float4*)x)[i];
    __half h0 = __float2half(v.x), h1 = __float2half(v.y);
    __half h2 = __float2half(v.z), h3 = __float2half(v.w);
    uint2 uh;
    uh.x = ((uint32_t)__half_as_ushort(h1) << 16) | __half_as_ushort(h0);
    uh.y = ((uint32_t)__half_as_ushort(h3) << 16) | __half_as_ushort(h2);
    ((uint2*)g_Xh)[i] = uh;
}

// ---------------- prep: transpose Wv -> fp16 ----------------
__global__ void k_split_wT(const float* __restrict__ wv) {
    __shared__ float t[32][33];
    int k0 = blockIdx.y * 32, n0 = blockIdx.x * 32;
    int tx = threadIdx.x, ty = threadIdx.y;   // (32, 8)
    #pragma unroll
    for (int j = 0; j < 32; j += 8)
        t[ty + j][tx] = wv[(size_t)(k0 + ty + j) * Dd + n0 + tx];
    __syncthreads();
    #pragma unroll
    for (int j = 0; j < 32; j += 8) {
        float v = t[tx][ty + j];
        size_t o = (size_t)(n0 + ty + j) * Dd + k0 + tx;
        g_Wth[o] = __float2half(v);
    }
}

// ---------------- Kernel 1: q = x[:, -1, :] @ wq + bq ----------------
__global__ void k_q(const float* __restrict__ x, const float* __restrict__ wq,
                    const float* __restrict__ bq) {
    __shared__ float xs[Dd];
    int b = blockIdx.x, jc = blockIdx.y;
    const float* xr = x + ((size_t)b*Ll + (Ll-1))*Dd;
    for (int i = threadIdx.x; i < Dd; i += 128) xs[i] = xr[i];
    __syncthreads();
    int j = jc*128 + threadIdx.x;
    float acc = bq[j];
    #pragma unroll 4
    for (int d = 0; d < Dd; d++) acc += xs[d] * wq[(size_t)d*Dd + j];
    g_q[b*Dd + j] = acc;
}

// ---------------- Kernel 2: G[b][h][din] ----------------
__global__ void __launch_bounds__(256) k_G(const float* __restrict__ wk) {
    __shared__ float qs[32][64];
    __shared__ float wks[64][128];
    int h = blockIdx.x, dg = blockIdx.y;   // grid (16, 8)
    int tid = threadIdx.x;
    int din0 = dg * 128;

    for (int i = tid; i < 512; i += 256) {
        int b = i >> 4, d4 = i & 15;
        ((float4*)&qs[b][0])[d4] = *(const float4*)&g_q[b*Dd + h*64 + d4*4];
    }
    for (int it = 0; it < 8; it++) {
        int i = tid + 256*it;
        int r = i >> 4, k4 = i & 15;
        float4 w = *(const float4*)&wk[(size_t)(din0 + r)*Dd + h*64 + k4*4];
        wks[k4*4 + 0][r] = w.x;
        wks[k4*4 + 1][r] = w.y;
        wks[k4*4 + 2][r] = w.z;
        wks[k4*4 + 3][r] = w.w;
    }
    __syncthreads();

    int dl = tid & 127, bg = tid >> 7;
    float acc[16];
    #pragma unroll
    for (int bi = 0; bi < 16; bi++) acc[bi] = 0.f;
    #pragma unroll 4
    for (int k = 0; k < 64; k++) {
        float wv = wks[k][dl];
        #pragma unroll
        for (int bi = 0; bi < 16; bi++)
            acc[bi] += wv * qs[bg*16 + bi][k];
    }
    #pragma unroll
    for (int bi = 0; bi < 16; bi++) {
        int b = bg*16 + bi;
        g_G[((size_t)b*Hh + h)*Dd + din0 + dl] = acc[bi];
    }
}

// ---------------- Kernel 2b ----------------
__global__ void k_c(const float* __restrict__ bk) {
    int t = blockIdx.x*blockDim.x + threadIdx.x;
    if (t >= Bb*Hh) return;
    int b = t >> 4, h = t & 15;
    float acc = 0.f;
    #pragma unroll 8
    for (int dv = 0; dv < DVv; dv++) {
        int j = h*DVv + dv;
        acc += bk[j] * g_q[b*Dd + j];
    }
    g_c[t] = acc;
}

// ---------------- Kernel 3: scores (register-tiled) ----------------
__global__ void __launch_bounds__(128) k_scores(const float* __restrict__ x) {
    __shared__ __align__(16) float Xs[128][68];
    __shared__ __align__(16) float Gs[16][72];
    int b = blockIdx.x, lt = blockIdx.y;
    int l0 = lt * 128;
    int tid = threadIdx.x;
    int tx = tid & 7, ty = tid >> 3;
    float acc[8][2];
    #pragma unroll
    for (int j = 0; j < 8; j++) { acc[j][0] = 0.f; acc[j][1] = 0.f; }
    const float* xb = x + ((size_t)b*Ll + l0)*Dd;
    const float* gb = g_G + (size_t)b*Hh*Dd;

    for (int k0 = 0; k0 < Dd; k0 += 64) {
        #pragma unroll
        for (int it = 0; it < 16; it++) {
            int i = tid + 128*it;
            int row = i >> 4, ks = i & 15;
            ((float4*)&Xs[row][0])[ks] = ((const float4*)(xb + (size_t)row*Dd + k0))[ks];
        }
        #pragma unroll
        for (int it = 0; it < 8; it++) {
            int e = tid + 128*it;
            int h = e >> 6, dnn = e & 63;
            Gs[h][dnn] = gb[(size_t)h*Dd + k0 + dnn];
        }
        __syncthreads();
        #pragma unroll
        for (int k4 = 0; k4 < 16; k4++) {
            float4 g0 = ((float4*)&Gs[2*tx][0])[k4];
            float4 g1 = ((float4*)&Gs[2*tx+1][0])[k4];
            #pragma unroll
            for (int j = 0; j < 8; j++) {
                float4 xv = ((float4*)&Xs[ty + 16*j][0])[k4];
                acc[j][0] += xv.x*g0.x + xv.y*g0.y + xv.z*g0.z + xv.w*g0.w;
                acc[j][1] += xv.x*g1.x + xv.y*g1.y + xv.z*g1.z + xv.w*g1.w;
            }
        }
        __syncthreads();
    }
    float invtemp = 1.0f / (32.0f + 1e-5f);
    float c0 = g_c[b*Hh + 2*tx], c1 = g_c[b*Hh + 2*tx + 1];
    #pragma unroll
    for (int j = 0; j < 8; j++) {
        int l = l0 + ty + 16*j;
        float rate = (float)(Ll - l - 1) * (1.0f/Ll) + 1.0f;
        g_S[((size_t)b*Hh + 2*tx)*Ll + l]     = rate * (acc[j][0] + c0) * invtemp;
        g_S[((size_t)b*Hh + 2*tx + 1)*Ll + l] = rate * (acc[j][1] + c1) * invtemp;
    }
}

// ---------------- Kernel 4: log-softmax ----------------
__global__ void k_lsm() {
    int bh = blockIdx.x;
    const float* s = g_S + (size_t)bh*Ll;
    __shared__ float red[8], red2[8];
    int tid = threadIdx.x, lane = tid & 31, warp = tid >> 5;
    float v[4]; float mx = -3.4e38f;
    #pragma unroll
    for (int i = 0; i < 4; i++) { v[i] = s[tid + 256*i]; mx = fmaxf(mx, v[i]); }
    #pragma unroll
    for (int o = 16; o > 0; o >>= 1) mx = fmaxf(mx, __shfl_xor_sync(0xffffffffu, mx, o));
    if (lane == 0) red[warp] = mx;
    __syncthreads();
    mx = red[0];
    #pragma unroll
    for (int i = 1; i < 8; i++) mx = fmaxf(mx, red[i]);
    float sum = 0.f;
    #pragma unroll
    for (int i = 0; i < 4; i++) sum += expf(v[i] - mx);
    #pragma unroll
    for (int o = 16; o > 0; o >>= 1) sum += __shfl_xor_sync(0xffffffffu, sum, o);
    if (lane == 0) red2[warp] = sum;
    __syncthreads();
    float tot = 0.f;
    #pragma unroll
    for (int i = 0; i < 8; i++) tot += red2[i];
    float lse = mx + logf(tot);
    int b = bh >> 4, h = bh & 15;
    #pragma unroll
    for (int i = 0; i < 4; i++) {
        int l = tid + 256*i;
        g_A[((size_t)b*Ll + l)*Hh + h] = v[i] - lse;
    }
}

// ---------------- Kernel 5: mma.sync single-pass fp16 V GEMM + epilogue ----------------
// CTA 128x128, 8 warps (2M x 4N), warp tile 64x32. K chunk 64, 3-stage cp.async,
// single barrier per chunk, 2 CTAs/SM.
#define RS2 144                      // smem row stride (bytes): 9*16 -> conflict-free ldmatrix
#define ATILE (128*RS2)              // 18432
#define OFF_BH2 ATILE
#define ST2 (2*ATILE)                // 36864 per stage
#define VG_SMEM (3*ST2)              // 110592
#define NCH 16

__global__ void __launch_bounds__(256, 2) k_vgemm_mma(
    const float* __restrict__ x, const float* __restrict__ bv, float* __restrict__ out)
{
    extern __shared__ __align__(128) char smem[];
    uint32_t smem_u = smem_to_u32(smem);
    int tid = threadIdx.x;
    int lane = tid & 31, wid = tid >> 5;
    int warpM = wid >> 2, warpN = wid & 3;
    int m_base = warpM * 64, n_base = warpN * 32;
    int ntile = blockIdx.x;          // 0..7
    int mtile = blockIdx.y;          // 0..255
    int row0 = mtile * 128;
    int col0 = ntile * 128;

    float acc[4][4][4];
    #pragma unroll
    for (int mf = 0; mf < 4; mf++)
        #pragma unroll
        for (int nf = 0; nf < 4; nf++)
            #pragma unroll
            for (int r = 0; r < 4; r++) acc[mf][nf][r] = 0.f;

    auto issue_chunk = [&](int c) {
        uint32_t sb = smem_u + (c % 3) * ST2;
        int k0 = c * 64;
        #pragma unroll
        for (int j = 0; j < 4; j++) {
            int i = tid + 256*j;
            int r = i >> 3, gg = i & 7;
            size_t ga = (size_t)(row0 + r)*Dd + k0 + gg*8;
            uint32_t sa = sb + r*RS2 + gg*16;
            cp16(sa, g_Xh + ga);
            size_t gbo = (size_t)(col0 + r)*Dd + k0 + gg*8;
            cp16(sa + OFF_BH2, g_Wth + gbo);
        }
        CP_COMMIT();
    };

    issue_chunk(0);
    issue_chunk(1);

    for (int c = 0; c < NCH; c++) {
        if (c == NCH - 1) { CP_WAIT(0); } else { CP_WAIT(1); }
        __syncthreads();
        if (c + 2 < NCH) issue_chunk(c + 2);

        uint32_t sb = smem_u + (c % 3) * ST2;
        int arow = lane & 15;
        int brow = (lane & 7) + ((lane >> 4) << 3);
        #pragma unroll
        for (int ks = 0; ks < 4; ks++) {
            int agr = ks*2 + (lane >> 4);
            int bgr = ks*2 + ((lane >> 3) & 1);
            uint32_t Ah[4][4];
            #pragma unroll
            for (int mf = 0; mf < 4; mf++) {
                uint32_t ad = sb + (m_base + mf*16 + arow)*RS2 + agr*16;
                LDM4(Ah[mf], ad);
            }
            uint32_t Bh[4][2];
            #pragma unroll
            for (int nn = 0; nn < 2; nn++) {
                uint32_t bd = sb + (n_base + nn*16 + brow)*RS2 + bgr*16;
                uint32_t r0, r1, r2, r3;
                asm volatile("ldmatrix.sync.aligned.m8n8.x4.shared.b16 {%0,%1,%2,%3}, [%4];"
                    : "=r"(r0), "=r"(r1), "=r"(r2), "=r"(r3) : "r"(bd + OFF_BH2));
                Bh[2*nn][0] = r0; Bh[2*nn][1] = r1; Bh[2*nn+1][0] = r2; Bh[2*nn+1][1] = r3;
            }
            #pragma unroll
            for (int mf = 0; mf < 4; mf++)
                #pragma unroll
                for (int nf = 0; nf < 4; nf++)
                    MMA(acc[mf][nf], Ah[mf], Bh[nf]);
        }
    }

    // ---- epilogue: out = a*(acc+bv) + x (pre-LN) ----
    int g = lane >> 2, cq = lane & 3;
    int hwarp = (col0 + n_base) >> 6;     // head constant per warp (32 <= 64)
    float aval[4][2];
    #pragma unroll
    for (int mf = 0; mf < 4; mf++)
        #pragma unroll
        for (int p = 0; p < 2; p++) {
            int row = row0 + m_base + mf*16 + g + p*8;
            int l = row & (Ll - 1), b = row >> 10;
            float rate = (float)(Ll - l - 1) * (1.0f/Ll) + 1.0f;
            aval[mf][p] = g_A[((size_t)b*Ll + l)*Hh + hwarp] * rate;
        }
    float2 bvv[4];
    #pragma unroll
    for (int nf = 0; nf < 4; nf++)
        bvv[nf] = *(const float2*)(bv + col0 + n_base + nf*8 + cq*2);

    #pragma unroll
    for (int mf = 0; mf < 4; mf++)
        #pragma unroll
        for (int p = 0; p < 2; p++) {
            int row = row0 + m_base + mf*16 + g + p*8;
            float a = aval[mf][p];
            #pragma unroll
            for (int nf = 0; nf < 4; nf++) {
                size_t o = (size_t)row*Dd + col0 + n_base + nf*8 + cq*2;
                float2 xr = *(const float2*)(x + o);
                float2 r;
                r.x = a*(acc[mf][nf][p*2]     + bvv[nf].x) + xr.x;
                r.y = a*(acc[mf][nf][p*2 + 1] + bvv[nf].y) + xr.y;
                *(float2*)(out + o) = r;
            }
        }
}

// ---------------- Kernel 6: in-place LayerNorm ----------------
__global__ void k_ln(float* __restrict__ out, const float* __restrict__ gamma,
                     const float* __restrict__ beta) {
    int row = blockIdx.x;
    float4* o4 = (float4*)(out + (size_t)row*Dd);
    int tid = threadIdx.x, lane = tid & 31, warp = tid >> 5;
    __shared__ float rs[8], rq[8];
    float4 v = o4[tid];
    float s = v.x + v.y + v.z + v.w;
    float q = v.x*v.x + v.y*v.y + v.z*v.z + v.w*v.w;
    #pragma unroll
    for (int o = 16; o > 0; o >>= 1) {
        s += __shfl_xor_sync(0xffffffffu, s, o);
        q += __shfl_xor_sync(0xffffffffu, q, o);
    }
    if (lane == 0) { rs[warp] = s; rq[warp] = q; }
    __syncthreads();
    s = 0.f; q = 0.f;
    #pragma unroll
    for (int i = 0; i < 8; i++) { s += rs[i]; q += rq[i]; }
    float mean = s * (1.0f/1024.0f);
    float var  = q * (1.0f/1024.0f) - mean*mean;
    float rstd = rsqrtf(var + 1e-5f);
    float4 gm = ((const float4*)gamma)[tid];
    float4 bb = ((const float4*)beta)[tid];
    v.x = (v.x - mean)*rstd*gm.x + bb.x;
    v.y = (v.y - mean)*rstd*gm.y + bb.y;
    v.z = (v.z - mean)*rstd*gm.z + bb.z;
    v.w = (v.w - mean)*rstd*gm.w + bb.w;
    o4[tid] = v;
}

extern "C" void kernel_launch(void* const* d_in, const int* in_sizes, int n_in,
                              void* d_out, int out_size) {
    const float* x     = (const float*)d_in[0];
    const float* wq    = (const float*)d_in[1];
    const float* bq    = (const float*)d_in[2];
    const float* wk    = (const float*)d_in[3];
    const float* bk    = (const float*)d_in[4];
    const float* wv    = (const float*)d_in[5];
    const float* bv    = (const float*)d_in[6];
    const float* gamma = (const float*)d_in[7];
    const float* beta  = (const float*)d_in[8];
    float* out = (float*)d_out;

    k_split_x<<<32768, 256>>>(x);
    k_split_wT<<<dim3(32, 32), dim3(32, 8)>>>(wv);
    k_q<<<dim3(Bb, 8), 128>>>(x, wq, bq);
    k_G<<<dim3(Hh, 8), 256>>>(wk);
    k_c<<<2, 256>>>(bk);
    k_scores<<<dim3(Bb, 8), 128>>>(x);
    k_lsm<<<Bb*Hh, 256>>>();

    cudaFuncSetAttribute(k_vgemm_mma, cudaFuncAttributeMaxDynamicSharedMemorySize, VG_SMEM);
    k_vgemm_mma<<<dim3(8, 256), 256, VG_SMEM>>>(x, bv, out);

    k_ln<<<Bb*Ll, 256>>>(out, gamma, beta);
}

// round 14
// speedup vs baseline: 5.9105x; 1.1344x over previous
#include <cuda_runtime.h>
#include <cuda_fp16.h>
#include <cstdint>

#define Bb 32
#define Ll 1024
#define Dd 1024
#define Hh 16
#define DVv 64

// ---------------- device-global scratch ----------------
__device__ float g_q[Bb*Dd];
__device__ __half g_Gh[Bb*Hh*Dd];           // [b][h][din] fp16
__device__ float g_c[Bb*Hh];
__device__ float g_S[Bb*Hh*Ll];
__device__ float g_A[Bb*Ll*Hh];
__device__ __half g_Xh[(size_t)Bb*Ll*Dd];   // 64 MB
__device__ __half g_Wth[(size_t)Dd*Dd];     // Wv^T hi  [n][k]

__device__ __forceinline__ uint32_t smem_to_u32(const void* p) {
    uint32_t a;
    asm("{ .reg .u64 t; cvta.to.shared.u64 t, %1; cvt.u32.u64 %0, t; }" : "=r"(a) : "l"(p));
    return a;
}
__device__ __forceinline__ void cp16(uint32_t saddr, const void* g) {
    asm volatile("cp.async.cg.shared.global [%0], [%1], 16;" :: "r"(saddr), "l"(g));
}
#define CP_COMMIT() asm volatile("cp.async.commit_group;" ::: "memory")
#define CP_WAIT(n)  asm volatile("cp.async.wait_group %0;" :: "n"(n) : "memory")

#define LDM4(R, addr) \
    asm volatile("ldmatrix.sync.aligned.m8n8.x4.shared.b16 {%0,%1,%2,%3}, [%4];" \
        : "=r"((R)[0]), "=r"((R)[1]), "=r"((R)[2]), "=r"((R)[3]) : "r"(addr))

#define MMA(D, A, B) \
    asm volatile("mma.sync.aligned.m16n8k16.row.col.f32.f16.f16.f32 " \
        "{%0,%1,%2,%3},{%4,%5,%6,%7},{%8,%9},{%0,%1,%2,%3};" \
        : "+f"((D)[0]), "+f"((D)[1]), "+f"((D)[2]), "+f"((D)[3]) \
        : "r"((A)[0]), "r"((A)[1]), "r"((A)[2]), "r"((A)[3]), "r"((B)[0]), "r"((B)[1]))

// ---------------- prep: X -> fp16 ----------------
__global__ void k_split_x(const float* __restrict__ x) {
    size_t i = (size_t)blockIdx.x * 256 + threadIdx.x;   // float4 index
    float4 v = ((const float4*)x)[i];
    __half h0 = __float2half(v.x), h1 = __float2half(v.y);
    __half h2 = __float2half(v.z), h3 = __float2half(v.w);
    uint2 uh;
    uh.x = ((uint32_t)__half_as_ushort(h1) << 16) | __half_as_ushort(h0);
    uh.y = ((uint32_t)__half_as_ushort(h3) << 16) | __half_as_ushort(h2);
    ((uint2*)g_Xh)[i] = uh;
}

// ---------------- prep: transpose Wv -> fp16 ----------------
__global__ void k_split_wT(const float* __restrict__ wv) {
    __shared__ float t[32][33];
    int k0 = blockIdx.y * 32, n0 = blockIdx.x * 32;
    int tx = threadIdx.x, ty = threadIdx.y;   // (32, 8)
    #pragma unroll
    for (int j = 0; j < 32; j += 8)
        t[ty + j][tx] = wv[(size_t)(k0 + ty + j) * Dd + n0 + tx];
    __syncthreads();
    #pragma unroll
    for (int j = 0; j < 32; j += 8) {
        float v = t[tx][ty + j];
        size_t o = (size_t)(n0 + ty + j) * Dd + k0 + tx;
        g_Wth[o] = __float2half(v);
    }
}

// ---------------- Kernel 1: q = x[:, -1, :] @ wq + bq ----------------
__global__ void k_q(const float* __restrict__ x, const float* __restrict__ wq,
                    const float* __restrict__ bq) {
    __shared__ float xs[Dd];
    int b = blockIdx.x, jc = blockIdx.y;
    const float* xr = x + ((size_t)b*Ll + (Ll-1))*Dd;
    for (int i = threadIdx.x; i < Dd; i += 128) xs[i] = xr[i];
    __syncthreads();
    int j = jc*128 + threadIdx.x;
    float acc = bq[j];
    #pragma unroll 4
    for (int d = 0; d < Dd; d++) acc += xs[d] * wq[(size_t)d*Dd + j];
    g_q[b*Dd + j] = acc;
}

// ---------------- Kernel 2: Gh[b][h][din] (fp16 out) ----------------
__global__ void __launch_bounds__(256) k_G(const float* __restrict__ wk) {
    __shared__ float qs[32][64];
    __shared__ float wks[64][128];
    int h = blockIdx.x, dg = blockIdx.y;   // grid (16, 8)
    int tid = threadIdx.x;
    int din0 = dg * 128;

    for (int i = tid; i < 512; i += 256) {
        int b = i >> 4, d4 = i & 15;
        ((float4*)&qs[b][0])[d4] = *(const float4*)&g_q[b*Dd + h*64 + d4*4];
    }
    for (int it = 0; it < 8; it++) {
        int i = tid + 256*it;
        int r = i >> 4, k4 = i & 15;
        float4 w = *(const float4*)&wk[(size_t)(din0 + r)*Dd + h*64 + k4*4];
        wks[k4*4 + 0][r] = w.x;
        wks[k4*4 + 1][r] = w.y;
        wks[k4*4 + 2][r] = w.z;
        wks[k4*4 + 3][r] = w.w;
    }
    __syncthreads();

    int dl = tid & 127, bg = tid >> 7;
    float acc[16];
    #pragma unroll
    for (int bi = 0; bi < 16; bi++) acc[bi] = 0.f;
    #pragma unroll 4
    for (int k = 0; k < 64; k++) {
        float wv = wks[k][dl];
        #pragma unroll
        for (int bi = 0; bi < 16; bi++)
            acc[bi] += wv * qs[bg*16 + bi][k];
    }
    #pragma unroll
    for (int bi = 0; bi < 16; bi++) {
        int b = bg*16 + bi;
        g_Gh[((size_t)b*Hh + h)*Dd + din0 + dl] = __float2half(acc[bi]);
    }
}

// ---------------- Kernel 2b ----------------
__global__ void k_c(const float* __restrict__ bk) {
    int t = blockIdx.x*blockDim.x + threadIdx.x;
    if (t >= Bb*Hh) return;
    int b = t >> 4, h = t & 15;
    float acc = 0.f;
    #pragma unroll 8
    for (int dv = 0; dv < DVv; dv++) {
        int j = h*DVv + dv;
        acc += bk[j] * g_q[b*Dd + j];
    }
    g_c[t] = acc;
}

// ---------------- Kernel 3: scores via mma.sync ----------------
#define SRS 144                      // A row stride bytes (128B data + 16 pad)
#define SAT (256*SRS)                // 36864 per A stage
#define BRS 2064                     // G row stride bytes (2048 + 16 pad)
#define OFF_G (3*SAT)                // 110592
#define SC_SMEM (OFF_G + 16*BRS)     // 143616

__global__ void __launch_bounds__(256) k_scores_tc() {
    extern __shared__ __align__(128) char smem[];
    uint32_t smem_u = smem_to_u32(smem);
    int b = blockIdx.x, mt = blockIdx.y;
    int l0 = mt * 256;
    int tid = threadIdx.x;
    int lane = tid & 31, w = tid >> 5;

    // load G[b] whole (16 x 1024 halves) into smem
    {
        const __half* gb = g_Gh + (size_t)b*Hh*Dd;
        #pragma unroll
        for (int j = 0; j < 8; j++) {
            int i = tid + 256*j;
            int r = i >> 7, seg = i & 127;
            cp16(smem_u + OFF_G + r*BRS + seg*16, gb + (size_t)r*Dd + seg*8);
        }
        CP_COMMIT();
    }
    // A chunk loader
    auto issue_a = [&](int c) {
        uint32_t sb = smem_u + (c % 3) * SAT;
        const __half* xb = g_Xh + ((size_t)b*Ll + l0)*Dd + c*64;
        #pragma unroll
        for (int j = 0; j < 8; j++) {
            int i = tid + 256*j;
            int r = i >> 3, seg = i & 7;
            cp16(sb + r*SRS + seg*16, xb + (size_t)r*Dd + seg*8);
        }
        CP_COMMIT();
    };
    issue_a(0);
    issue_a(1);

    float acc[2][2][4];
    #pragma unroll
    for (int mf = 0; mf < 2; mf++)
        #pragma unroll
        for (int nf = 0; nf < 2; nf++)
            #pragma unroll
            for (int r = 0; r < 4; r++) acc[mf][nf][r] = 0.f;

    int arow = lane & 15;
    int brow = (lane & 7) + ((lane >> 4) << 3);
    for (int c = 0; c < 16; c++) {
        if (c == 15) { CP_WAIT(0); } else { CP_WAIT(1); }   // drain last group!
        __syncthreads();
        if (c + 2 < 16) issue_a(c + 2);

        uint32_t sb = smem_u + (c % 3) * SAT;
        #pragma unroll
        for (int ks = 0; ks < 4; ks++) {
            uint32_t Ah[2][4];
            #pragma unroll
            for (int mf = 0; mf < 2; mf++) {
                uint32_t ad = sb + (w*32 + mf*16 + arow)*SRS + (ks*2 + (lane >> 4))*16;
                LDM4(Ah[mf], ad);
            }
            uint32_t Bh[2][2];
            {
                uint32_t bd = smem_u + OFF_G + brow*BRS + c*128 + ks*32 + ((lane >> 3) & 1)*16;
                uint32_t r0, r1, r2, r3;
                asm volatile("ldmatrix.sync.aligned.m8n8.x4.shared.b16 {%0,%1,%2,%3}, [%4];"
                    : "=r"(r0), "=r"(r1), "=r"(r2), "=r"(r3) : "r"(bd));
                Bh[0][0] = r0; Bh[0][1] = r1; Bh[1][0] = r2; Bh[1][1] = r3;
            }
            #pragma unroll
            for (int mf = 0; mf < 2; mf++)
                #pragma unroll
                for (int nf = 0; nf < 2; nf++)
                    MMA(acc[mf][nf], Ah[mf], Bh[nf]);
        }
        __syncthreads();
    }

    // epilogue: s = rate * (acc + c[b][h]) / temp  -> g_S[(b*16+h)*1024 + l]
    float invtemp = 1.0f / (32.0f + 1e-5f);
    int g = lane >> 2, cq = lane & 3;
    #pragma unroll
    for (int mf = 0; mf < 2; mf++)
        #pragma unroll
        for (int p = 0; p < 2; p++) {
            int l = l0 + w*32 + mf*16 + g + p*8;
            float rate = (float)(Ll - l - 1) * (1.0f/Ll) + 1.0f;
            #pragma unroll
            for (int nf = 0; nf < 2; nf++) {
                int h0 = nf*8 + cq*2;
                float c0 = g_c[b*Hh + h0], c1 = g_c[b*Hh + h0 + 1];
                g_S[((size_t)b*Hh + h0)*Ll + l]     = rate * (acc[mf][nf][p*2]     + c0) * invtemp;
                g_S[((size_t)b*Hh + h0 + 1)*Ll + l] = rate * (acc[mf][nf][p*2 + 1] + c1) * invtemp;
            }
        }
}

// ---------------- Kernel 4: log-softmax ----------------
__global__ void k_lsm() {
    int bh = blockIdx.x;
    const float* s = g_S + (size_t)bh*Ll;
    __shared__ float red[8], red2[8];
    int tid = threadIdx.x, lane = tid & 31, warp = tid >> 5;
    float v[4]; float mx = -3.4e38f;
    #pragma unroll
    for (int i = 0; i < 4; i++) { v[i] = s[tid + 256*i]; mx = fmaxf(mx, v[i]); }
    #pragma unroll
    for (int o = 16; o > 0; o >>= 1) mx = fmaxf(mx, __shfl_xor_sync(0xffffffffu, mx, o));
    if (lane == 0) red[warp] = mx;
    __syncthreads();
    mx = red[0];
    #pragma unroll
    for (int i = 1; i < 8; i++) mx = fmaxf(mx, red[i]);
    float sum = 0.f;
    #pragma unroll
    for (int i = 0; i < 4; i++) sum += expf(v[i] - mx);
    #pragma unroll
    for (int o = 16; o > 0; o >>= 1) sum += __shfl_xor_sync(0xffffffffu, sum, o);
    if (lane == 0) red2[warp] = sum;
    __syncthreads();
    float tot = 0.f;
    #pragma unroll
    for (int i = 0; i < 8; i++) tot += red2[i];
    float lse = mx + logf(tot);
    int b = bh >> 4, h = bh & 15;
    #pragma unroll
    for (int i = 0; i < 4; i++) {
        int l = tid + 256*i;
        g_A[((size_t)b*Ll + l)*Hh + h] = v[i] - lse;
    }
}

// ---------------- Kernel 5: mma.sync single-pass fp16 V GEMM + epilogue ----------------
#define RS2 144
#define ATILE (128*RS2)              // 18432
#define OFF_BH2 ATILE
#define ST2 (2*ATILE)                // 36864 per stage
#define VG_SMEM (3*ST2)              // 110592
#define NCH 16

__global__ void __launch_bounds__(256, 2) k_vgemm_mma(
    const float* __restrict__ x, const float* __restrict__ bv, float* __restrict__ out)
{
    extern __shared__ __align__(128) char smem[];
    uint32_t smem_u = smem_to_u32(smem);
    int tid = threadIdx.x;
    int lane = tid & 31, wid = tid >> 5;
    int warpM = wid >> 2, warpN = wid & 3;
    int m_base = warpM * 64, n_base = warpN * 32;
    int ntile = blockIdx.x;          // 0..7
    int mtile = blockIdx.y;          // 0..255
    int row0 = mtile * 128;
    int col0 = ntile * 128;

    float acc[4][4][4];
    #pragma unroll
    for (int mf = 0; mf < 4; mf++)
        #pragma unroll
        for (int nf = 0; nf < 4; nf++)
            #pragma unroll
            for (int r = 0; r < 4; r++) acc[mf][nf][r] = 0.f;

    auto issue_chunk = [&](int c) {
        uint32_t sb = smem_u + (c % 3) * ST2;
        int k0 = c * 64;
        #pragma unroll
        for (int j = 0; j < 4; j++) {
            int i = tid + 256*j;
            int r = i >> 3, gg = i & 7;
            size_t ga = (size_t)(row0 + r)*Dd + k0 + gg*8;
            uint32_t sa = sb + r*RS2 + gg*16;
            cp16(sa, g_Xh + ga);
            size_t gbo = (size_t)(col0 + r)*Dd + k0 + gg*8;
            cp16(sa + OFF_BH2, g_Wth + gbo);
        }
        CP_COMMIT();
    };

    issue_chunk(0);
    issue_chunk(1);

    for (int c = 0; c < NCH; c++) {
        if (c == NCH - 1) { CP_WAIT(0); } else { CP_WAIT(1); }
        __syncthreads();
        if (c + 2 < NCH) issue_chunk(c + 2);

        uint32_t sb = smem_u + (c % 3) * ST2;
        int arow = lane & 15;
        int brow = (lane & 7) + ((lane >> 4) << 3);
        #pragma unroll
        for (int ks = 0; ks < 4; ks++) {
            int agr = ks*2 + (lane >> 4);
            int bgr = ks*2 + ((lane >> 3) & 1);
            uint32_t Ah[4][4];
            #pragma unroll
            for (int mf = 0; mf < 4; mf++) {
                uint32_t ad = sb + (m_base + mf*16 + arow)*RS2 + agr*16;
                LDM4(Ah[mf], ad);
            }
            uint32_t Bh[4][2];
            #pragma unroll
            for (int nn = 0; nn < 2; nn++) {
                uint32_t bd = sb + (n_base + nn*16 + brow)*RS2 + bgr*16;
                uint32_t r0, r1, r2, r3;
                asm volatile("ldmatrix.sync.aligned.m8n8.x4.shared.b16 {%0,%1,%2,%3}, [%4];"
                    : "=r"(r0), "=r"(r1), "=r"(r2), "=r"(r3) : "r"(bd + OFF_BH2));
                Bh[2*nn][0] = r0; Bh[2*nn][1] = r1; Bh[2*nn+1][0] = r2; Bh[2*nn+1][1] = r3;
            }
            #pragma unroll
            for (int mf = 0; mf < 4; mf++)
                #pragma unroll
                for (int nf = 0; nf < 4; nf++)
                    MMA(acc[mf][nf], Ah[mf], Bh[nf]);
        }
    }

    // ---- epilogue: out = a*(acc+bv) + x (pre-LN) ----
    int g = lane >> 2, cq = lane & 3;
    int hwarp = (col0 + n_base) >> 6;
    float aval[4][2];
    #pragma unroll
    for (int mf = 0; mf < 4; mf++)
        #pragma unroll
        for (int p = 0; p < 2; p++) {
            int row = row0 + m_base + mf*16 + g + p*8;
            int l = row & (Ll - 1), b = row >> 10;
            float rate = (float)(Ll - l - 1) * (1.0f/Ll) + 1.0f;
            aval[mf][p] = g_A[((size_t)b*Ll + l)*Hh + hwarp] * rate;
        }
    float2 bvv[4];
    #pragma unroll
    for (int nf = 0; nf < 4; nf++)
        bvv[nf] = *(const float2*)(bv + col0 + n_base + nf*8 + cq*2);

    #pragma unroll
    for (int mf = 0; mf < 4; mf++)
        #pragma unroll
        for (int p = 0; p < 2; p++) {
            int row = row0 + m_base + mf*16 + g + p*8;
            float a = aval[mf][p];
            #pragma unroll
            for (int nf = 0; nf < 4; nf++) {
                size_t o = (size_t)row*Dd + col0 + n_base + nf*8 + cq*2;
                float2 xr = *(const float2*)(x + o);
                float2 r;
                r.x = a*(acc[mf][nf][p*2]     + bvv[nf].x) + xr.x;
                r.y = a*(acc[mf][nf][p*2 + 1] + bvv[nf].y) + xr.y;
                *(float2*)(out + o) = r;
            }
        }
}

// ---------------- Kernel 6: in-place LayerNorm ----------------
__global__ void k_ln(float* __restrict__ out, const float* __restrict__ gamma,
                     const float* __restrict__ beta) {
    int row = blockIdx.x;
    float4* o4 = (float4*)(out + (size_t)row*Dd);
    int tid = threadIdx.x, lane = tid & 31, warp = tid >> 5;
    __shared__ float rs[8], rq[8];
    float4 v = o4[tid];
    float s = v.x + v.y + v.z + v.w;
    float q = v.x*v.x + v.y*v.y + v.z*v.z + v.w*v.w;
    #pragma unroll
    for (int o = 16; o > 0; o >>= 1) {
        s += __shfl_xor_sync(0xffffffffu, s, o);
        q += __shfl_xor_sync(0xffffffffu, q, o);
    }
    if (lane == 0) { rs[warp] = s; rq[warp] = q; }
    __syncthreads();
    s = 0.f; q = 0.f;
    #pragma unroll
    for (int i = 0; i < 8; i++) { s += rs[i]; q += rq[i]; }
    float mean = s * (1.0f/1024.0f);
    float var  = q * (1.0f/1024.0f) - mean*mean;
    float rstd = rsqrtf(var + 1e-5f);
    float4 gm = ((const float4*)gamma)[tid];
    float4 bb = ((const float4*)beta)[tid];
    v.x = (v.x - mean)*rstd*gm.x + bb.x;
    v.y = (v.y - mean)*rstd*gm.y + bb.y;
    v.z = (v.z - mean)*rstd*gm.z + bb.z;
    v.w = (v.w - mean)*rstd*gm.w + bb.w;
    o4[tid] = v;
}

extern "C" void kernel_launch(void* const* d_in, const int* in_sizes, int n_in,
                              void* d_out, int out_size) {
    const float* x     = (const float*)d_in[0];
    const float* wq    = (const float*)d_in[1];
    const float* bq    = (const float*)d_in[2];
    const float* wk    = (const float*)d_in[3];
    const float* bk    = (const float*)d_in[4];
    const float* wv    = (const float*)d_in[5];
    const float* bv    = (const float*)d_in[6];
    const float* gamma = (const float*)d_in[7];
    const float* beta  = (const float*)d_in[8];
    float* out = (float*)d_out;

    k_split_x<<<32768, 256>>>(x);
    k_split_wT<<<dim3(32, 32), dim3(32, 8)>>>(wv);
    k_q<<<dim3(Bb, 8), 128>>>(x, wq, bq);
    k_G<<<dim3(Hh, 8), 256>>>(wk);
    k_c<<<2, 256>>>(bk);

    cudaFuncSetAttribute(k_scores_tc, cudaFuncAttributeMaxDynamicSharedMemorySize, SC_SMEM);
    k_scores_tc<<<dim3(Bb, 4), 256, SC_SMEM>>>();

    k_lsm<<<Bb*Hh, 256>>>();

    cudaFuncSetAttribute(k_vgemm_mma, cudaFuncAttributeMaxDynamicSharedMemorySize, VG_SMEM);
    k_vgemm_mma<<<dim3(8, 256), 256, VG_SMEM>>>(x, bv, out);

    k_ln<<<Bb*Ll, 256>>>(out, gamma, beta);
}